// round 6
// baseline (speedup 1.0000x reference)
#include <cuda_runtime.h>
#include <cuda_bf16.h>
#include <cuda_fp16.h>
#include <math.h>
#include <stdint.h>

#define NN 50000
#define EE 300000
#define DD 256
#define FF 1024
#define CC 40
#define AB_PITCH 80

// ---------------- scratch (static device globals; no allocation) ----------------
__device__ float g_X[NN * DD];
__device__ float g_ns[NN];
__device__ float g_nd[NN];
__device__ int   g_degout[NN];
__device__ int   g_degin[NN];
__device__ int   g_fill[NN];
__device__ int   g_incl[49 * 1024];
__device__ int   g_bsum[64];
__device__ int   g_boff[64];
__device__ int   g_rowptr[NN + 1];
__device__ int   g_col[EE];
__device__ float g_bns[DD];
__device__ float g_bnq[DD];

// packed split-bf16 A planes written by spmm: per (rowblk, ktile): 128 rows x 80B
__device__ __align__(16) unsigned char g_Ah[391 * 8 * 10240];
__device__ __align__(16) unsigned char g_Al[391 * 8 * 10240];

// fc weights: single fp16 plane, per ktile 256 n-rows x 80B
__device__ __align__(16) unsigned char g_Wfc16[32 * 20480];
// layer weights: split bf16 hi/lo planes
__device__ __align__(16) unsigned char g_W1_h[8 * 20480];
__device__ __align__(16) unsigned char g_W1_l[8 * 20480];
__device__ __align__(16) unsigned char g_W2_h[8 * 20480];
__device__ __align__(16) unsigned char g_W2_l[8 * 20480];
__device__ __align__(16) unsigned char g_W3_h[8 * 20480];
__device__ __align__(16) unsigned char g_W3_l[8 * 20480];

// ================= helpers =================
__device__ __forceinline__ uint32_t smem_to_u32(const void* p) {
    uint32_t a;
    asm("{ .reg .u64 t; cvta.to.shared.u64 t, %1; cvt.u32.u64 %0, t; }" : "=r"(a) : "l"(p));
    return a;
}
__device__ __forceinline__ void ldm4(uint32_t* r, uint32_t addr) {
    asm volatile("ldmatrix.sync.aligned.m8n8.x4.shared.b16 {%0,%1,%2,%3}, [%4];"
        : "=r"(r[0]), "=r"(r[1]), "=r"(r[2]), "=r"(r[3]) : "r"(addr));
}
__device__ __forceinline__ void mma_bf16(float* d, const uint32_t* a, const uint32_t* b) {
    asm volatile(
        "mma.sync.aligned.m16n8k16.row.col.f32.bf16.bf16.f32 "
        "{%0,%1,%2,%3}, {%4,%5,%6,%7}, {%8,%9}, {%0,%1,%2,%3};"
        : "+f"(d[0]), "+f"(d[1]), "+f"(d[2]), "+f"(d[3])
        : "r"(a[0]), "r"(a[1]), "r"(a[2]), "r"(a[3]), "r"(b[0]), "r"(b[1]));
}
__device__ __forceinline__ void mma_f16(float* d, const uint32_t* a, const uint32_t* b) {
    asm volatile(
        "mma.sync.aligned.m16n8k16.row.col.f32.f16.f16.f32 "
        "{%0,%1,%2,%3}, {%4,%5,%6,%7}, {%8,%9}, {%0,%1,%2,%3};"
        : "+f"(d[0]), "+f"(d[1]), "+f"(d[2]), "+f"(d[3])
        : "r"(a[0]), "r"(a[1]), "r"(a[2]), "r"(a[3]), "r"(b[0]), "r"(b[1]));
}
__device__ __forceinline__ void cp16(uint32_t saddr, const void* gaddr) {
    asm volatile("cp.async.cg.shared.global [%0], [%1], 16;" :: "r"(saddr), "l"(gaddr));
}
#define CP_COMMIT() asm volatile("cp.async.commit_group;" ::: "memory")
#define CP_WAIT0()  asm volatile("cp.async.wait_group 0;" ::: "memory")

__device__ __forceinline__ void split2(float x0, float x1, uint32_t& ph, uint32_t& pl) {
    __nv_bfloat16 h0 = __float2bfloat16(x0), h1 = __float2bfloat16(x1);
    float r0 = x0 - __bfloat162float(h0), r1 = x1 - __bfloat162float(h1);
    __nv_bfloat16 l0 = __float2bfloat16(r0), l1 = __float2bfloat16(r1);
    ph = ((uint32_t)__bfloat16_as_ushort(h1) << 16) | (uint32_t)__bfloat16_as_ushort(h0);
    pl = ((uint32_t)__bfloat16_as_ushort(l1) << 16) | (uint32_t)__bfloat16_as_ushort(l0);
}
__device__ __forceinline__ void split2h(float x0, float x1, uint32_t& ph, uint32_t& pl) {
    __half h0 = __float2half_rn(x0), h1 = __float2half_rn(x1);
    float r0 = x0 - __half2float(h0), r1 = x1 - __half2float(h1);
    __half l0 = __float2half_rn(r0), l1 = __float2half_rn(r1);
    ph = ((uint32_t)__half_as_ushort(h1) << 16) | (uint32_t)__half_as_ushort(h0);
    pl = ((uint32_t)__half_as_ushort(l1) << 16) | (uint32_t)__half_as_ushort(l0);
}
__device__ __forceinline__ uint32_t pack2h(float x0, float x1) {
    __half h0 = __float2half_rn(x0), h1 = __float2half_rn(x1);
    return ((uint32_t)__half_as_ushort(h1) << 16) | (uint32_t)__half_as_ushort(h0);
}

// ---------------- graph prep ----------------
__global__ void k_zero_prep() {
    int i = blockIdx.x * 256 + threadIdx.x;
    if (i < NN) { g_degout[i] = 0; g_degin[i] = 0; g_fill[i] = 0; }
}
__global__ void k_count(const int* __restrict__ src, const int* __restrict__ dst) {
    int e = blockIdx.x * 256 + threadIdx.x;
    if (e < EE) { atomicAdd(&g_degout[src[e]], 1); atomicAdd(&g_degin[dst[e]], 1); }
}
__global__ void k_norms() {
    int i = blockIdx.x * 256 + threadIdx.x;
    if (i < NN) {
        g_ns[i] = rsqrtf((float)max(g_degout[i], 1));
        g_nd[i] = rsqrtf((float)max(g_degin[i], 1));
    }
}
__global__ void k_scan1() {
    __shared__ int s[1024];
    int tid = threadIdx.x;
    int i = blockIdx.x * 1024 + tid;
    int v = (i < NN) ? g_degin[i] : 0;
    s[tid] = v;
    __syncthreads();
    for (int off = 1; off < 1024; off <<= 1) {
        int t = (tid >= off) ? s[tid - off] : 0;
        __syncthreads(); s[tid] += t; __syncthreads();
    }
    g_incl[i] = s[tid];
    if (tid == 1023) g_bsum[blockIdx.x] = s[1023];
}
__global__ void k_scan2() {
    __shared__ int s[64];
    int tid = threadIdx.x;
    int v = (tid < 49) ? g_bsum[tid] : 0;
    s[tid] = v;
    __syncthreads();
    for (int off = 1; off < 64; off <<= 1) {
        int t = (tid >= off) ? s[tid - off] : 0;
        __syncthreads(); s[tid] += t; __syncthreads();
    }
    g_boff[tid] = s[tid] - v;
}
__global__ void k_scan3() {
    int i = blockIdx.x * 256 + threadIdx.x;
    if (i < NN) g_rowptr[i + 1] = g_incl[i] + g_boff[i >> 10];
    if (i == 0) g_rowptr[0] = 0;
}
__global__ void k_fill(const int* __restrict__ src, const int* __restrict__ dst) {
    int e = blockIdx.x * 256 + threadIdx.x;
    if (e < EE) {
        int d = dst[e];
        int pos = g_rowptr[d] + atomicAdd(&g_fill[d], 1);
        g_col[pos] = src[e];
    }
}

// ---------------- SpMM gather -> packed split-bf16 planes (norm_d fused) ----------------
__global__ void k_spmm(const float* __restrict__ X) {
    int node = blockIdx.x * 8 + threadIdx.y;
    if (node >= NN) return;
    int lane = threadIdx.x;
    float4 a0 = make_float4(0.f, 0.f, 0.f, 0.f);
    float4 a1 = make_float4(0.f, 0.f, 0.f, 0.f);
    int beg = g_rowptr[node], end = g_rowptr[node + 1];
    for (int e = beg; e < end; e++) {
        int s = g_col[e];
        float w = g_ns[s];
        const float4* row = (const float4*)(X + (size_t)s * DD);
        float4 v = row[lane];
        a0.x += w * v.x; a0.y += w * v.y; a0.z += w * v.z; a0.w += w * v.w;
        v = row[lane + 32];
        a1.x += w * v.x; a1.y += w * v.y; a1.z += w * v.z; a1.w += w * v.w;
    }
    float nd = g_nd[node];
    a0.x *= nd; a0.y *= nd; a0.z *= nd; a0.w *= nd;
    a1.x *= nd; a1.y *= nd; a1.z *= nd; a1.w *= nd;

    int kt = lane >> 3;
    size_t rb = (size_t)(node >> 7) * 8;
    uint32_t roff = (uint32_t)((node & 127) * AB_PITCH + (lane & 7) * 8);
    uint32_t h0, l0, h1, l1;

    split2(a0.x, a0.y, h0, l0);
    split2(a0.z, a0.w, h1, l1);
    size_t base = (rb + kt) * 10240 + roff;
    *(uint2*)(g_Ah + base) = make_uint2(h0, h1);
    *(uint2*)(g_Al + base) = make_uint2(l0, l1);

    split2(a1.x, a1.y, h0, l0);
    split2(a1.z, a1.w, h1, l1);
    base = (rb + 4 + kt) * 10240 + roff;
    *(uint2*)(g_Ah + base) = make_uint2(h0, h1);
    *(uint2*)(g_Al + base) = make_uint2(l0, l1);
}

// ---------------- weight prepack (bf16 split, layers) ----------------
__global__ void k_prepack(const float* __restrict__ W, unsigned char* __restrict__ ph,
                          unsigned char* __restrict__ pl, int K) {
    int task = blockIdx.x * 256 + threadIdx.x;
    int nk8 = K >> 3;
    if (task >= DD * nk8) return;
    int n = task / nk8, k8 = task % nk8;
    int k0 = k8 << 3;
    float x[8];
    #pragma unroll
    for (int i = 0; i < 8; i++) x[i] = W[(size_t)(k0 + i) * DD + n];
    uint4 vh, vl;
    split2(x[0], x[1], vh.x, vl.x);
    split2(x[2], x[3], vh.y, vl.y);
    split2(x[4], x[5], vh.z, vl.z);
    split2(x[6], x[7], vh.w, vl.w);
    size_t off = (size_t)(k0 >> 5) * 20480 + (size_t)n * AB_PITCH + (k0 & 31) * 2;
    *(uint4*)(ph + off) = vh;
    *(uint4*)(pl + off) = vl;
}

// ---------------- weight prepack (fp16 single, fc) ----------------
__global__ void k_prepack16(const float* __restrict__ W, unsigned char* __restrict__ p, int K) {
    int task = blockIdx.x * 256 + threadIdx.x;
    int nk8 = K >> 3;
    if (task >= DD * nk8) return;
    int n = task / nk8, k8 = task % nk8;
    int k0 = k8 << 3;
    float x[8];
    #pragma unroll
    for (int i = 0; i < 8; i++) x[i] = W[(size_t)(k0 + i) * DD + n];
    uint4 v;
    v.x = pack2h(x[0], x[1]);
    v.y = pack2h(x[2], x[3]);
    v.z = pack2h(x[4], x[5]);
    v.w = pack2h(x[6], x[7]);
    size_t off = (size_t)(k0 >> 5) * 20480 + (size_t)n * AB_PITCH + (k0 & 31) * 2;
    *(uint4*)(p + off) = v;
}

// ================= merged-N HMMA GEMM cores =================
// CTA 128x256, 512 thr, warps 4x4, warp tile 32x64

// ---- fc: fp32 A split on the fly to fp16 hi/lo, B single fp16 ----
// buffer 40960: Ah@0(10240) Al@10240 B@20480(20480); x2
#define SMEM_FC16 81920
__global__ void __launch_bounds__(512) hmma_gemm_fc16(
    const float* __restrict__ A, const unsigned char* __restrict__ B_g,
    const float* __restrict__ bias, float* __restrict__ C, int M, int K)
{
    extern __shared__ __align__(16) unsigned char smem[];
    uint32_t sb = smem_to_u32(smem);
    int tid = threadIdx.x;
    int wid = tid >> 5, lane = tid & 31;
    int bm0 = blockIdx.x * 128;
    int nIter = K >> 5;

    int arow = tid >> 2;
    int akq = (tid & 3) * 8;
    int agr = bm0 + arow;
    bool avalid = (agr < M);
    const float* aptr = A + (size_t)(avalid ? agr : 0) * K + akq;
    uint32_t a_soff = (uint32_t)(arow * AB_PITCH + akq * 2);

    int wr = wid >> 2, wc = wid & 3;
    int mbase_w = wr * 32;
    int nbase_w = wc * 64;

    int lj = lane >> 3, lr = lane & 7;
    uint32_t aoffA = (uint32_t)(((lj & 1) * 8 + lr) * AB_PITCH + (lj >> 1) * 16);
    uint32_t aoffB = (uint32_t)(((lj >> 1) * 8 + lr) * AB_PITCH + (lj & 1) * 16);

    float acc[2][8][4];
    #pragma unroll
    for (int mt = 0; mt < 2; mt++)
        #pragma unroll
        for (int nt = 0; nt < 8; nt++)
            #pragma unroll
            for (int i = 0; i < 4; i++) acc[mt][nt][i] = 0.f;

    {
        for (int c = tid; c < 1280; c += 512)
            cp16(sb + 20480 + c * 16, B_g + c * 16);
        CP_COMMIT();
        float4 v0 = make_float4(0.f, 0.f, 0.f, 0.f), v1 = v0;
        if (avalid) { v0 = *(const float4*)(aptr); v1 = *(const float4*)(aptr + 4); }
        uint4 vh, vl;
        split2h(v0.x, v0.y, vh.x, vl.x);
        split2h(v0.z, v0.w, vh.y, vl.y);
        split2h(v1.x, v1.y, vh.z, vl.z);
        split2h(v1.z, v1.w, vh.w, vl.w);
        *(uint4*)(smem + a_soff) = vh;
        *(uint4*)(smem + 10240 + a_soff) = vl;
        CP_WAIT0();
        __syncthreads();
    }

    for (int it = 0; it < nIter; it++) {
        uint32_t bufo = (uint32_t)((it & 1) * 40960);
        uint32_t nbufo = (uint32_t)(((it + 1) & 1) * 40960);
        bool more = (it + 1 < nIter);

        float4 v0 = make_float4(0.f, 0.f, 0.f, 0.f), v1 = v0;
        if (more) {
            size_t tb = (size_t)(it + 1) * 20480;
            for (int c = tid; c < 1280; c += 512)
                cp16(sb + nbufo + 20480 + c * 16, B_g + tb + c * 16);
            CP_COMMIT();
            if (avalid) {
                int k0 = (it + 1) << 5;
                v0 = *(const float4*)(aptr + k0);
                v1 = *(const float4*)(aptr + k0 + 4);
            }
        }

        #pragma unroll
        for (int ks = 0; ks < 2; ks++) {
            uint32_t kof = (uint32_t)(ks * 32);
            uint32_t ah[2][4], al[2][4];
            #pragma unroll
            for (int mt = 0; mt < 2; mt++) {
                uint32_t base = sb + bufo + (uint32_t)((mbase_w + mt * 16) * AB_PITCH) + kof + aoffA;
                ldm4(ah[mt], base);
                ldm4(al[mt], base + 10240);
            }
            #pragma unroll
            for (int np = 0; np < 4; np++) {
                uint32_t bbase = sb + bufo + 20480 + (uint32_t)((nbase_w + np * 16) * AB_PITCH) + kof + aoffB;
                uint32_t rh[4];
                ldm4(rh, bbase);
                #pragma unroll
                for (int mt = 0; mt < 2; mt++) {
                    mma_f16(acc[mt][np * 2 + 0], ah[mt], rh + 0);
                    mma_f16(acc[mt][np * 2 + 0], al[mt], rh + 0);
                    mma_f16(acc[mt][np * 2 + 1], ah[mt], rh + 2);
                    mma_f16(acc[mt][np * 2 + 1], al[mt], rh + 2);
                }
            }
        }

        if (more) {
            uint4 vh, vl;
            split2h(v0.x, v0.y, vh.x, vl.x);
            split2h(v0.z, v0.w, vh.y, vl.y);
            split2h(v1.x, v1.y, vh.z, vl.z);
            split2h(v1.z, v1.w, vh.w, vl.w);
            *(uint4*)(smem + nbufo + a_soff) = vh;
            *(uint4*)(smem + nbufo + 10240 + a_soff) = vl;
            CP_WAIT0();
        }
        __syncthreads();
    }

    int g = lane >> 2, t2 = (lane & 3) * 2;
    #pragma unroll
    for (int mt = 0; mt < 2; mt++) {
        int r0 = bm0 + mbase_w + mt * 16 + g;
        int r1 = r0 + 8;
        #pragma unroll
        for (int nt = 0; nt < 8; nt++) {
            int c = nbase_w + nt * 8 + t2;
            float b0 = __ldg(&bias[c]), b1 = __ldg(&bias[c + 1]);
            if (r0 < M) *(float2*)(C + (size_t)r0 * DD + c) =
                make_float2(acc[mt][nt][0] + b0, acc[mt][nt][1] + b1);
            if (r1 < M) *(float2*)(C + (size_t)r1 * DD + c) =
                make_float2(acc[mt][nt][2] + b0, acc[mt][nt][3] + b1);
        }
    }
}

// ---- layer GEMM: packed split-bf16 A, split-bf16 B, optional fused BN stats ----
#define SMEM_GEMM 122880
template <bool STATS>
__global__ void __launch_bounds__(512) hmma_gemm_pk(
    const unsigned char* __restrict__ Ah_g, const unsigned char* __restrict__ Al_g,
    const unsigned char* __restrict__ Bh_g, const unsigned char* __restrict__ Bl_g,
    const float* __restrict__ bias, float* __restrict__ C, int M)
{
    extern __shared__ __align__(16) unsigned char smem[];
    uint32_t sb = smem_to_u32(smem);
    int tid = threadIdx.x;
    int wid = tid >> 5, lane = tid & 31;
    int bm0 = blockIdx.x * 128;
    const int nIter = 8;
    size_t abase = (size_t)blockIdx.x * 8 * 10240;

    int wr = wid >> 2, wc = wid & 3;
    int mbase_w = wr * 32;
    int nbase_w = wc * 64;

    int lj = lane >> 3, lr = lane & 7;
    uint32_t aoffA = (uint32_t)(((lj & 1) * 8 + lr) * AB_PITCH + (lj >> 1) * 16);
    uint32_t aoffB = (uint32_t)(((lj >> 1) * 8 + lr) * AB_PITCH + (lj & 1) * 16);

    float acc[2][8][4];
    #pragma unroll
    for (int mt = 0; mt < 2; mt++)
        #pragma unroll
        for (int nt = 0; nt < 8; nt++)
            #pragma unroll
            for (int i = 0; i < 4; i++) acc[mt][nt][i] = 0.f;

    {
        for (int c = tid; c < 640; c += 512) {
            cp16(sb + c * 16, Ah_g + abase + c * 16);
            cp16(sb + 10240 + c * 16, Al_g + abase + c * 16);
        }
        for (int c = tid; c < 1280; c += 512) {
            cp16(sb + 20480 + c * 16, Bh_g + c * 16);
            cp16(sb + 40960 + c * 16, Bl_g + c * 16);
        }
        CP_COMMIT();
        CP_WAIT0();
        __syncthreads();
    }

    for (int it = 0; it < nIter; it++) {
        uint32_t bufo = (uint32_t)((it & 1) * 61440);
        uint32_t nbufo = (uint32_t)(((it + 1) & 1) * 61440);
        bool more = (it + 1 < nIter);

        if (more) {
            size_t ta = abase + (size_t)(it + 1) * 10240;
            size_t tb = (size_t)(it + 1) * 20480;
            for (int c = tid; c < 640; c += 512) {
                cp16(sb + nbufo + c * 16, Ah_g + ta + c * 16);
                cp16(sb + nbufo + 10240 + c * 16, Al_g + ta + c * 16);
            }
            for (int c = tid; c < 1280; c += 512) {
                cp16(sb + nbufo + 20480 + c * 16, Bh_g + tb + c * 16);
                cp16(sb + nbufo + 40960 + c * 16, Bl_g + tb + c * 16);
            }
            CP_COMMIT();
        }

        #pragma unroll
        for (int ks = 0; ks < 2; ks++) {
            uint32_t kof = (uint32_t)(ks * 32);
            uint32_t ah[2][4], al[2][4];
            #pragma unroll
            for (int mt = 0; mt < 2; mt++) {
                uint32_t base = sb + bufo + (uint32_t)((mbase_w + mt * 16) * AB_PITCH) + kof + aoffA;
                ldm4(ah[mt], base);
                ldm4(al[mt], base + 10240);
            }
            #pragma unroll
            for (int np = 0; np < 4; np++) {
                uint32_t bbase = sb + bufo + 20480 + (uint32_t)((nbase_w + np * 16) * AB_PITCH) + kof + aoffB;
                uint32_t rh[4], rl[4];
                ldm4(rh, bbase);
                ldm4(rl, bbase + 20480);
                #pragma unroll
                for (int mt = 0; mt < 2; mt++) {
                    mma_bf16(acc[mt][np * 2 + 0], ah[mt], rh + 0);
                    mma_bf16(acc[mt][np * 2 + 0], ah[mt], rl + 0);
                    mma_bf16(acc[mt][np * 2 + 0], al[mt], rh + 0);
                    mma_bf16(acc[mt][np * 2 + 1], ah[mt], rh + 2);
                    mma_bf16(acc[mt][np * 2 + 1], ah[mt], rl + 2);
                    mma_bf16(acc[mt][np * 2 + 1], al[mt], rh + 2);
                }
            }
        }

        if (more) CP_WAIT0();
        __syncthreads();
    }

    int g = lane >> 2, t2 = (lane & 3) * 2;
    #pragma unroll
    for (int nt = 0; nt < 8; nt++) {
        int c = nbase_w + nt * 8 + t2;
        float b0 = __ldg(&bias[c]), b1 = __ldg(&bias[c + 1]);
        float s0 = 0.f, s1 = 0.f, q0 = 0.f, q1 = 0.f;
        #pragma unroll
        for (int mt = 0; mt < 2; mt++) {
            int r0 = bm0 + mbase_w + mt * 16 + g;
            int r1 = r0 + 8;
            if (r0 < M) {
                float v0 = acc[mt][nt][0] + b0, v1 = acc[mt][nt][1] + b1;
                *(float2*)(C + (size_t)r0 * DD + c) = make_float2(v0, v1);
                if (STATS) { s0 += v0; q0 += v0 * v0; s1 += v1; q1 += v1 * v1; }
            }
            if (r1 < M) {
                float v0 = acc[mt][nt][2] + b0, v1 = acc[mt][nt][3] + b1;
                *(float2*)(C + (size_t)r1 * DD + c) = make_float2(v0, v1);
                if (STATS) { s0 += v0; q0 += v0 * v0; s1 += v1; q1 += v1 * v1; }
            }
        }
        if (STATS) {
            #pragma unroll
            for (int o = 4; o <= 16; o <<= 1) {
                s0 += __shfl_xor_sync(0xffffffffu, s0, o);
                s1 += __shfl_xor_sync(0xffffffffu, s1, o);
                q0 += __shfl_xor_sync(0xffffffffu, q0, o);
                q1 += __shfl_xor_sync(0xffffffffu, q1, o);
            }
            if (g == 0) {
                atomicAdd(&g_bns[c], s0);
                atomicAdd(&g_bns[c + 1], s1);
                atomicAdd(&g_bnq[c], q0);
                atomicAdd(&g_bnq[c + 1], q1);
            }
        }
    }
}

// ---------------- BatchNorm + ELU ----------------
__global__ void k_zero_bn() {
    int c = threadIdx.x;
    g_bns[c] = 0.f;
    g_bnq[c] = 0.f;
}
__global__ void k_bn_apply(float* __restrict__ X,
                           const float* __restrict__ gamma,
                           const float* __restrict__ beta) {
    int idx = blockIdx.x * 256 + threadIdx.x;
    if (idx >= NN * (DD / 4)) return;
    int c4 = idx & 63;
    int c = c4 * 4;
    const float invN = 1.f / (float)NN;
    float4 sm = *(const float4*)&g_bns[c];
    float4 sq = *(const float4*)&g_bnq[c];
    float4 gm = *(const float4*)&gamma[c];
    float4 bt = *(const float4*)&beta[c];
    float mu, var, sc;
    float4 x = ((float4*)X)[idx];
    float4 y;
    mu = sm.x * invN; var = sq.x * invN - mu * mu; sc = gm.x * rsqrtf(var + 1e-5f);
    y.x = sc * (x.x - mu) + bt.x;
    mu = sm.y * invN; var = sq.y * invN - mu * mu; sc = gm.y * rsqrtf(var + 1e-5f);
    y.y = sc * (x.y - mu) + bt.y;
    mu = sm.z * invN; var = sq.z * invN - mu * mu; sc = gm.z * rsqrtf(var + 1e-5f);
    y.z = sc * (x.z - mu) + bt.z;
    mu = sm.w * invN; var = sq.w * invN - mu * mu; sc = gm.w * rsqrtf(var + 1e-5f);
    y.w = sc * (x.w - mu) + bt.w;
    y.x = (y.x > 0.f) ? y.x : (__expf(y.x) - 1.f);
    y.y = (y.y > 0.f) ? y.y : (__expf(y.y) - 1.f);
    y.z = (y.z > 0.f) ? y.z : (__expf(y.z) - 1.f);
    y.w = (y.w > 0.f) ? y.w : (__expf(y.w) - 1.f);
    ((float4*)X)[idx] = y;
}

// ---------------- logits GEMM ----------------
__global__ __launch_bounds__(320) void k_logits(
    const float* __restrict__ X, const float* __restrict__ W,
    const float* __restrict__ bias, float* __restrict__ O, int M)
{
    __shared__ float Xs[32][68];
    __shared__ float Ws[32][40];
    int tid = threadIdx.x;
    int bm0 = blockIdx.x * 64;
    int rg = tid / 40;
    int col = tid % 40;
    float acc[8];
    #pragma unroll
    for (int i = 0; i < 8; i++) acc[i] = 0.f;

    for (int k0 = 0; k0 < DD; k0 += 32) {
        for (int idx = tid; idx < 512; idx += 320) {
            int row = idx >> 3;
            int kq = idx & 7;
            float4 v = make_float4(0.f, 0.f, 0.f, 0.f);
            int gr = bm0 + row;
            if (gr < M) v = *(const float4*)(X + (size_t)gr * DD + k0 + kq * 4);
            Xs[kq * 4 + 0][row] = v.x;
            Xs[kq * 4 + 1][row] = v.y;
            Xs[kq * 4 + 2][row] = v.z;
            Xs[kq * 4 + 3][row] = v.w;
        }
        for (int idx = tid; idx < 1280; idx += 320) {
            int k = idx / 40, c = idx % 40;
            Ws[k][c] = W[(size_t)(k0 + k) * CC + c];
        }
        __syncthreads();
        #pragma unroll
        for (int kk = 0; kk < 32; kk++) {
            float w = Ws[kk][col];
            float a0[4], a1[4];
            *(float4*)&a0[0] = *(float4*)&Xs[kk][rg * 8];
            *(float4*)&a1[0] = *(float4*)&Xs[kk][rg * 8 + 4];
            acc[0] += a0[0] * w; acc[1] += a0[1] * w;
            acc[2] += a0[2] * w; acc[3] += a0[3] * w;
            acc[4] += a1[0] * w; acc[5] += a1[1] * w;
            acc[6] += a1[2] * w; acc[7] += a1[3] * w;
        }
        __syncthreads();
    }
    float b = bias[col];
    #pragma unroll
    for (int i = 0; i < 8; i++) {
        int r = bm0 + rg * 8 + i;
        if (r < M) O[(size_t)r * CC + col] = acc[i] + b;
    }
}

// ---------------- static stream/event init ----------------
struct SideRes {
    cudaStream_t sB;
    cudaEvent_t evFork, evJoin;
    SideRes() {
        cudaStreamCreateWithFlags(&sB, cudaStreamNonBlocking);
        cudaEventCreateWithFlags(&evFork, cudaEventDisableTiming);
        cudaEventCreateWithFlags(&evJoin, cudaEventDisableTiming);
        cudaFuncSetAttribute(hmma_gemm_fc16, cudaFuncAttributeMaxDynamicSharedMemorySize, SMEM_FC16);
        cudaFuncSetAttribute(hmma_gemm_pk<true>,  cudaFuncAttributeMaxDynamicSharedMemorySize, SMEM_GEMM);
        cudaFuncSetAttribute(hmma_gemm_pk<false>, cudaFuncAttributeMaxDynamicSharedMemorySize, SMEM_GEMM);
    }
};
static SideRes g_sr;

// ---------------- driver ----------------
extern "C" void kernel_launch(void* const* d_in, const int* in_sizes, int n_in,
                              void* d_out, int out_size)
{
    const float* feat  = (const float*)d_in[0];
    const int*   src   = (const int*)d_in[1];
    const int*   dst   = (const int*)d_in[2];
    const float* W_fc  = (const float*)d_in[3];
    const float* b_fc  = (const float*)d_in[4];
    const float* W1    = (const float*)d_in[5];
    const float* b1    = (const float*)d_in[6];
    const float* W2    = (const float*)d_in[7];
    const float* b2    = (const float*)d_in[8];
    const float* W3    = (const float*)d_in[9];
    const float* b3    = (const float*)d_in[10];
    const float* gamma = (const float*)d_in[11];
    const float* beta  = (const float*)d_in[12];
    const float* W_lin = (const float*)d_in[13];
    const float* b_lin = (const float*)d_in[14];
    float* out = (float*)d_out;

    float* gX;  cudaGetSymbolAddress((void**)&gX, g_X);
    unsigned char *gAh, *gAl;
    cudaGetSymbolAddress((void**)&gAh, g_Ah);
    cudaGetSymbolAddress((void**)&gAl, g_Al);
    unsigned char *pF16, *p1h, *p1l, *p2h, *p2l, *p3h, *p3l;
    cudaGetSymbolAddress((void**)&pF16, g_Wfc16);
    cudaGetSymbolAddress((void**)&p1h, g_W1_h);
    cudaGetSymbolAddress((void**)&p1l, g_W1_l);
    cudaGetSymbolAddress((void**)&p2h, g_W2_h);
    cudaGetSymbolAddress((void**)&p2l, g_W2_l);
    cudaGetSymbolAddress((void**)&p3h, g_W3_h);
    cudaGetSymbolAddress((void**)&p3l, g_W3_l);

    const int NB_N = (NN + 255) / 256;
    const int NB_E = (EE + 255) / 256;
    const int GEMM_GRID = (NN + 127) / 128;  // 391
    dim3 spmm_block(32, 8);
    int spmm_grid = (NN + 7) / 8;
    int bn_grid = (NN * (DD / 4) + 255) / 256;

    // fork: side stream does graph prep + layer-weight prepack + bn zero
    cudaEventRecord(g_sr.evFork, 0);
    cudaStreamWaitEvent(g_sr.sB, g_sr.evFork, 0);

    k_zero_prep<<<NB_N, 256, 0, g_sr.sB>>>();
    k_count<<<NB_E, 256, 0, g_sr.sB>>>(src, dst);
    k_norms<<<NB_N, 256, 0, g_sr.sB>>>();
    k_scan1<<<49, 1024, 0, g_sr.sB>>>();
    k_scan2<<<1, 64, 0, g_sr.sB>>>();
    k_scan3<<<NB_N, 256, 0, g_sr.sB>>>();
    k_fill<<<NB_E, 256, 0, g_sr.sB>>>(src, dst);
    k_prepack<<<(DD * (DD / 8) + 255) / 256, 256, 0, g_sr.sB>>>(W1, p1h, p1l, DD);
    k_prepack<<<(DD * (DD / 8) + 255) / 256, 256, 0, g_sr.sB>>>(W2, p2h, p2l, DD);
    k_prepack<<<(DD * (DD / 8) + 255) / 256, 256, 0, g_sr.sB>>>(W3, p3h, p3l, DD);
    k_zero_bn<<<1, 256, 0, g_sr.sB>>>();
    cudaEventRecord(g_sr.evJoin, g_sr.sB);

    // main stream: fc prepack + fc GEMM
    k_prepack16<<<(DD * (FF / 8) + 255) / 256, 256>>>(W_fc, pF16, FF);
    hmma_gemm_fc16<<<GEMM_GRID, 512, SMEM_FC16>>>(feat, pF16, b_fc, gX, NN, FF);

    // join
    cudaStreamWaitEvent(0, g_sr.evJoin, 0);

    // layer 1 (stats fused into GEMM epilogue)
    k_spmm<<<spmm_grid, spmm_block>>>(gX);
    hmma_gemm_pk<true><<<GEMM_GRID, 512, SMEM_GEMM>>>(gAh, gAl, p1h, p1l, b1, gX, NN);
    k_bn_apply<<<bn_grid, 256>>>(gX, gamma, beta);
    k_zero_bn<<<1, 256>>>();

    // layer 2
    k_spmm<<<spmm_grid, spmm_block>>>(gX);
    hmma_gemm_pk<true><<<GEMM_GRID, 512, SMEM_GEMM>>>(gAh, gAl, p2h, p2l, b2, gX, NN);
    k_bn_apply<<<bn_grid, 256>>>(gX, gamma, beta);

    // layer 3 -> features into d_out[0 : N*D)
    k_spmm<<<spmm_grid, spmm_block>>>(gX);
    hmma_gemm_pk<false><<<GEMM_GRID, 512, SMEM_GEMM>>>(gAh, gAl, p3h, p3l, b3, out, NN);

    // logits -> d_out[N*D : )
    k_logits<<<(NN + 63) / 64, 320>>>(out, W_lin, b_lin, out + (size_t)NN * DD, NN);
}

// round 7
// speedup vs baseline: 1.3099x; 1.3099x over previous
#include <cuda_runtime.h>
#include <cuda_bf16.h>
#include <math.h>
#include <stdint.h>

#define NN 50000
#define EE 300000
#define DD 256
#define FF 1024
#define CC 40
#define AB_PITCH 80

// ---------------- scratch (static device globals; no allocation) ----------------
__device__ float g_X[NN * DD];
__device__ float g_ns[NN];
__device__ float g_nd[NN];
__device__ int   g_degout[NN];
__device__ int   g_degin[NN];
__device__ int   g_fill[NN];
__device__ int   g_incl[49 * 1024];
__device__ int   g_bsum[64];
__device__ int   g_boff[64];
__device__ int   g_rowptr[NN + 1];
__device__ int   g_col[EE];
__device__ float g_bns[DD];
__device__ float g_bnq[DD];

// packed split-bf16 A planes written by spmm: per (rowblk, ktile): 128 rows x 80B
__device__ __align__(16) unsigned char g_Ah[391 * 8 * 10240];
__device__ __align__(16) unsigned char g_Al[391 * 8 * 10240];

// prepacked weights: per ktile: 256 n-rows x 80B = 20480 B (bf16 hi/lo planes)
__device__ __align__(16) unsigned char g_Wfc_h[32 * 20480];
__device__ __align__(16) unsigned char g_Wfc_l[32 * 20480];
__device__ __align__(16) unsigned char g_W1_h[8 * 20480];
__device__ __align__(16) unsigned char g_W1_l[8 * 20480];
__device__ __align__(16) unsigned char g_W2_h[8 * 20480];
__device__ __align__(16) unsigned char g_W2_l[8 * 20480];
__device__ __align__(16) unsigned char g_W3_h[8 * 20480];
__device__ __align__(16) unsigned char g_W3_l[8 * 20480];

// ================= helpers =================
__device__ __forceinline__ uint32_t smem_to_u32(const void* p) {
    uint32_t a;
    asm("{ .reg .u64 t; cvta.to.shared.u64 t, %1; cvt.u32.u64 %0, t; }" : "=r"(a) : "l"(p));
    return a;
}
__device__ __forceinline__ void ldm4(uint32_t* r, uint32_t addr) {
    asm volatile("ldmatrix.sync.aligned.m8n8.x4.shared.b16 {%0,%1,%2,%3}, [%4];"
        : "=r"(r[0]), "=r"(r[1]), "=r"(r[2]), "=r"(r[3]) : "r"(addr));
}
__device__ __forceinline__ void mma_bf16(float* d, const uint32_t* a, const uint32_t* b) {
    asm volatile(
        "mma.sync.aligned.m16n8k16.row.col.f32.bf16.bf16.f32 "
        "{%0,%1,%2,%3}, {%4,%5,%6,%7}, {%8,%9}, {%0,%1,%2,%3};"
        : "+f"(d[0]), "+f"(d[1]), "+f"(d[2]), "+f"(d[3])
        : "r"(a[0]), "r"(a[1]), "r"(a[2]), "r"(a[3]), "r"(b[0]), "r"(b[1]));
}
__device__ __forceinline__ void cp16(uint32_t saddr, const void* gaddr) {
    asm volatile("cp.async.cg.shared.global [%0], [%1], 16;" :: "r"(saddr), "l"(gaddr));
}
#define CP_COMMIT() asm volatile("cp.async.commit_group;" ::: "memory")
#define CP_WAIT0()  asm volatile("cp.async.wait_group 0;" ::: "memory")

__device__ __forceinline__ void split2(float x0, float x1, uint32_t& ph, uint32_t& pl) {
    __nv_bfloat16 h0 = __float2bfloat16(x0), h1 = __float2bfloat16(x1);
    float r0 = x0 - __bfloat162float(h0), r1 = x1 - __bfloat162float(h1);
    __nv_bfloat16 l0 = __float2bfloat16(r0), l1 = __float2bfloat16(r1);
    ph = ((uint32_t)__bfloat16_as_ushort(h1) << 16) | (uint32_t)__bfloat16_as_ushort(h0);
    pl = ((uint32_t)__bfloat16_as_ushort(l1) << 16) | (uint32_t)__bfloat16_as_ushort(l0);
}

// ---------------- graph prep ----------------
__global__ void k_zero_prep() {
    int i = blockIdx.x * 256 + threadIdx.x;
    if (i < NN) { g_degout[i] = 0; g_degin[i] = 0; g_fill[i] = 0; }
}
__global__ void k_count(const int* __restrict__ src, const int* __restrict__ dst) {
    int e = blockIdx.x * 256 + threadIdx.x;
    if (e < EE) { atomicAdd(&g_degout[src[e]], 1); atomicAdd(&g_degin[dst[e]], 1); }
}
__global__ void k_norms() {
    int i = blockIdx.x * 256 + threadIdx.x;
    if (i < NN) {
        g_ns[i] = rsqrtf((float)max(g_degout[i], 1));
        g_nd[i] = rsqrtf((float)max(g_degin[i], 1));
    }
}
__global__ void k_scan1() {
    __shared__ int s[1024];
    int tid = threadIdx.x;
    int i = blockIdx.x * 1024 + tid;
    int v = (i < NN) ? g_degin[i] : 0;
    s[tid] = v;
    __syncthreads();
    for (int off = 1; off < 1024; off <<= 1) {
        int t = (tid >= off) ? s[tid - off] : 0;
        __syncthreads(); s[tid] += t; __syncthreads();
    }
    g_incl[i] = s[tid];
    if (tid == 1023) g_bsum[blockIdx.x] = s[1023];
}
__global__ void k_scan2() {
    __shared__ int s[64];
    int tid = threadIdx.x;
    int v = (tid < 49) ? g_bsum[tid] : 0;
    s[tid] = v;
    __syncthreads();
    for (int off = 1; off < 64; off <<= 1) {
        int t = (tid >= off) ? s[tid - off] : 0;
        __syncthreads(); s[tid] += t; __syncthreads();
    }
    g_boff[tid] = s[tid] - v;
}
__global__ void k_scan3() {
    int i = blockIdx.x * 256 + threadIdx.x;
    if (i < NN) g_rowptr[i + 1] = g_incl[i] + g_boff[i >> 10];
    if (i == 0) g_rowptr[0] = 0;
}
__global__ void k_fill(const int* __restrict__ src, const int* __restrict__ dst) {
    int e = blockIdx.x * 256 + threadIdx.x;
    if (e < EE) {
        int d = dst[e];
        int pos = g_rowptr[d] + atomicAdd(&g_fill[d], 1);
        g_col[pos] = src[e];
    }
}

// ---------------- SpMM gather -> packed split-bf16 planes (norm_d fused) ----------------
__global__ void k_spmm(const float* __restrict__ X) {
    int node = blockIdx.x * 8 + threadIdx.y;
    if (node >= NN) return;
    int lane = threadIdx.x;
    float4 a0 = make_float4(0.f, 0.f, 0.f, 0.f);
    float4 a1 = make_float4(0.f, 0.f, 0.f, 0.f);
    int beg = g_rowptr[node], end = g_rowptr[node + 1];
    for (int e = beg; e < end; e++) {
        int s = g_col[e];
        float w = g_ns[s];
        const float4* row = (const float4*)(X + (size_t)s * DD);
        float4 v = row[lane];
        a0.x += w * v.x; a0.y += w * v.y; a0.z += w * v.z; a0.w += w * v.w;
        v = row[lane + 32];
        a1.x += w * v.x; a1.y += w * v.y; a1.z += w * v.z; a1.w += w * v.w;
    }
    float nd = g_nd[node];
    a0.x *= nd; a0.y *= nd; a0.z *= nd; a0.w *= nd;
    a1.x *= nd; a1.y *= nd; a1.z *= nd; a1.w *= nd;

    int kt = lane >> 3;
    size_t rb = (size_t)(node >> 7) * 8;
    uint32_t roff = (uint32_t)((node & 127) * AB_PITCH + (lane & 7) * 8);
    uint32_t h0, l0, h1, l1;

    split2(a0.x, a0.y, h0, l0);
    split2(a0.z, a0.w, h1, l1);
    size_t base = (rb + kt) * 10240 + roff;
    *(uint2*)(g_Ah + base) = make_uint2(h0, h1);
    *(uint2*)(g_Al + base) = make_uint2(l0, l1);

    split2(a1.x, a1.y, h0, l0);
    split2(a1.z, a1.w, h1, l1);
    base = (rb + 4 + kt) * 10240 + roff;
    *(uint2*)(g_Ah + base) = make_uint2(h0, h1);
    *(uint2*)(g_Al + base) = make_uint2(l0, l1);
}

// ---------------- weight prepack (bf16 split) ----------------
__global__ void k_prepack(const float* __restrict__ W, unsigned char* __restrict__ ph,
                          unsigned char* __restrict__ pl, int K) {
    int task = blockIdx.x * 256 + threadIdx.x;
    int nk8 = K >> 3;
    if (task >= DD * nk8) return;
    int n = task / nk8, k8 = task % nk8;
    int k0 = k8 << 3;
    float x[8];
    #pragma unroll
    for (int i = 0; i < 8; i++) x[i] = W[(size_t)(k0 + i) * DD + n];
    uint4 vh, vl;
    split2(x[0], x[1], vh.x, vl.x);
    split2(x[2], x[3], vh.y, vl.y);
    split2(x[4], x[5], vh.z, vl.z);
    split2(x[6], x[7], vh.w, vl.w);
    size_t off = (size_t)(k0 >> 5) * 20480 + (size_t)n * AB_PITCH + (k0 & 31) * 2;
    *(uint4*)(ph + off) = vh;
    *(uint4*)(pl + off) = vl;
}

// ================= merged-N HMMA GEMM cores (bf16 3-product) =================
// CTA 128x256, 512 thr, warps 4x4, warp tile 32x64
// smem buffer 61440: Ah@0(10240) Al@10240 Bh@20480(20480) Bl@40960(20480); x2
#define SMEM_GEMM 122880

// ---- fc: fp32 A split on the fly ----
__global__ void __launch_bounds__(512) hmma_gemm_fc(
    const float* __restrict__ A,
    const unsigned char* __restrict__ Bh_g, const unsigned char* __restrict__ Bl_g,
    const float* __restrict__ bias, float* __restrict__ C, int M, int K)
{
    extern __shared__ __align__(16) unsigned char smem[];
    uint32_t sb = smem_to_u32(smem);
    int tid = threadIdx.x;
    int wid = tid >> 5, lane = tid & 31;
    int bm0 = blockIdx.x * 128;
    int nIter = K >> 5;

    int arow = tid >> 2;
    int akq = (tid & 3) * 8;
    int agr = bm0 + arow;
    bool avalid = (agr < M);
    const float* aptr = A + (size_t)(avalid ? agr : 0) * K + akq;
    uint32_t a_soff = (uint32_t)(arow * AB_PITCH + akq * 2);

    int wr = wid >> 2, wc = wid & 3;
    int mbase_w = wr * 32;
    int nbase_w = wc * 64;

    int lj = lane >> 3, lr = lane & 7;
    uint32_t aoffA = (uint32_t)(((lj & 1) * 8 + lr) * AB_PITCH + (lj >> 1) * 16);
    uint32_t aoffB = (uint32_t)(((lj >> 1) * 8 + lr) * AB_PITCH + (lj & 1) * 16);

    float acc[2][8][4];
    #pragma unroll
    for (int mt = 0; mt < 2; mt++)
        #pragma unroll
        for (int nt = 0; nt < 8; nt++)
            #pragma unroll
            for (int i = 0; i < 4; i++) acc[mt][nt][i] = 0.f;

    {
        for (int c = tid; c < 1280; c += 512) {
            cp16(sb + 20480 + c * 16, Bh_g + c * 16);
            cp16(sb + 40960 + c * 16, Bl_g + c * 16);
        }
        CP_COMMIT();
        float4 v0 = make_float4(0.f, 0.f, 0.f, 0.f), v1 = v0;
        if (avalid) { v0 = *(const float4*)(aptr); v1 = *(const float4*)(aptr + 4); }
        uint4 vh, vl;
        split2(v0.x, v0.y, vh.x, vl.x);
        split2(v0.z, v0.w, vh.y, vl.y);
        split2(v1.x, v1.y, vh.z, vl.z);
        split2(v1.z, v1.w, vh.w, vl.w);
        *(uint4*)(smem + a_soff) = vh;
        *(uint4*)(smem + 10240 + a_soff) = vl;
        CP_WAIT0();
        __syncthreads();
    }

    for (int it = 0; it < nIter; it++) {
        uint32_t bufo = (uint32_t)((it & 1) * 61440);
        uint32_t nbufo = (uint32_t)(((it + 1) & 1) * 61440);
        bool more = (it + 1 < nIter);

        float4 v0 = make_float4(0.f, 0.f, 0.f, 0.f), v1 = v0;
        if (more) {
            size_t tb = (size_t)(it + 1) * 20480;
            for (int c = tid; c < 1280; c += 512) {
                cp16(sb + nbufo + 20480 + c * 16, Bh_g + tb + c * 16);
                cp16(sb + nbufo + 40960 + c * 16, Bl_g + tb + c * 16);
            }
            CP_COMMIT();
            if (avalid) {
                int k0 = (it + 1) << 5;
                v0 = *(const float4*)(aptr + k0);
                v1 = *(const float4*)(aptr + k0 + 4);
            }
        }

        #pragma unroll
        for (int ks = 0; ks < 2; ks++) {
            uint32_t kof = (uint32_t)(ks * 32);
            uint32_t ah[2][4], al[2][4];
            #pragma unroll
            for (int mt = 0; mt < 2; mt++) {
                uint32_t base = sb + bufo + (uint32_t)((mbase_w + mt * 16) * AB_PITCH) + kof + aoffA;
                ldm4(ah[mt], base);
                ldm4(al[mt], base + 10240);
            }
            #pragma unroll
            for (int np = 0; np < 4; np++) {
                uint32_t bbase = sb + bufo + 20480 + (uint32_t)((nbase_w + np * 16) * AB_PITCH) + kof + aoffB;
                uint32_t rh[4], rl[4];
                ldm4(rh, bbase);
                ldm4(rl, bbase + 20480);
                #pragma unroll
                for (int mt = 0; mt < 2; mt++) {
                    mma_bf16(acc[mt][np * 2 + 0], ah[mt], rh + 0);
                    mma_bf16(acc[mt][np * 2 + 0], ah[mt], rl + 0);
                    mma_bf16(acc[mt][np * 2 + 0], al[mt], rh + 0);
                    mma_bf16(acc[mt][np * 2 + 1], ah[mt], rh + 2);
                    mma_bf16(acc[mt][np * 2 + 1], ah[mt], rl + 2);
                    mma_bf16(acc[mt][np * 2 + 1], al[mt], rh + 2);
                }
            }
        }

        if (more) {
            uint4 vh, vl;
            split2(v0.x, v0.y, vh.x, vl.x);
            split2(v0.z, v0.w, vh.y, vl.y);
            split2(v1.x, v1.y, vh.z, vl.z);
            split2(v1.z, v1.w, vh.w, vl.w);
            *(uint4*)(smem + nbufo + a_soff) = vh;
            *(uint4*)(smem + nbufo + 10240 + a_soff) = vl;
            CP_WAIT0();
        }
        __syncthreads();
    }

    int g = lane >> 2, t2 = (lane & 3) * 2;
    #pragma unroll
    for (int mt = 0; mt < 2; mt++) {
        int r0 = bm0 + mbase_w + mt * 16 + g;
        int r1 = r0 + 8;
        #pragma unroll
        for (int nt = 0; nt < 8; nt++) {
            int c = nbase_w + nt * 8 + t2;
            float b0 = __ldg(&bias[c]), b1 = __ldg(&bias[c + 1]);
            if (r0 < M) *(float2*)(C + (size_t)r0 * DD + c) =
                make_float2(acc[mt][nt][0] + b0, acc[mt][nt][1] + b1);
            if (r1 < M) *(float2*)(C + (size_t)r1 * DD + c) =
                make_float2(acc[mt][nt][2] + b0, acc[mt][nt][3] + b1);
        }
    }
}

// ---- layer GEMM: packed split-bf16 A, optional fused BN stats ----
template <bool STATS>
__global__ void __launch_bounds__(512) hmma_gemm_pk(
    const unsigned char* __restrict__ Ah_g, const unsigned char* __restrict__ Al_g,
    const unsigned char* __restrict__ Bh_g, const unsigned char* __restrict__ Bl_g,
    const float* __restrict__ bias, float* __restrict__ C, int M)
{
    extern __shared__ __align__(16) unsigned char smem[];
    uint32_t sb = smem_to_u32(smem);
    int tid = threadIdx.x;
    int wid = tid >> 5, lane = tid & 31;
    int bm0 = blockIdx.x * 128;
    const int nIter = 8;
    size_t abase = (size_t)blockIdx.x * 8 * 10240;

    int wr = wid >> 2, wc = wid & 3;
    int mbase_w = wr * 32;
    int nbase_w = wc * 64;

    int lj = lane >> 3, lr = lane & 7;
    uint32_t aoffA = (uint32_t)(((lj & 1) * 8 + lr) * AB_PITCH + (lj >> 1) * 16);
    uint32_t aoffB = (uint32_t)(((lj >> 1) * 8 + lr) * AB_PITCH + (lj & 1) * 16);

    float acc[2][8][4];
    #pragma unroll
    for (int mt = 0; mt < 2; mt++)
        #pragma unroll
        for (int nt = 0; nt < 8; nt++)
            #pragma unroll
            for (int i = 0; i < 4; i++) acc[mt][nt][i] = 0.f;

    {
        for (int c = tid; c < 640; c += 512) {
            cp16(sb + c * 16, Ah_g + abase + c * 16);
            cp16(sb + 10240 + c * 16, Al_g + abase + c * 16);
        }
        for (int c = tid; c < 1280; c += 512) {
            cp16(sb + 20480 + c * 16, Bh_g + c * 16);
            cp16(sb + 40960 + c * 16, Bl_g + c * 16);
        }
        CP_COMMIT();
        CP_WAIT0();
        __syncthreads();
    }

    for (int it = 0; it < nIter; it++) {
        uint32_t bufo = (uint32_t)((it & 1) * 61440);
        uint32_t nbufo = (uint32_t)(((it + 1) & 1) * 61440);
        bool more = (it + 1 < nIter);

        if (more) {
            size_t ta = abase + (size_t)(it + 1) * 10240;
            size_t tb = (size_t)(it + 1) * 20480;
            for (int c = tid; c < 640; c += 512) {
                cp16(sb + nbufo + c * 16, Ah_g + ta + c * 16);
                cp16(sb + nbufo + 10240 + c * 16, Al_g + ta + c * 16);
            }
            for (int c = tid; c < 1280; c += 512) {
                cp16(sb + nbufo + 20480 + c * 16, Bh_g + tb + c * 16);
                cp16(sb + nbufo + 40960 + c * 16, Bl_g + tb + c * 16);
            }
            CP_COMMIT();
        }

        #pragma unroll
        for (int ks = 0; ks < 2; ks++) {
            uint32_t kof = (uint32_t)(ks * 32);
            uint32_t ah[2][4], al[2][4];
            #pragma unroll
            for (int mt = 0; mt < 2; mt++) {
                uint32_t base = sb + bufo + (uint32_t)((mbase_w + mt * 16) * AB_PITCH) + kof + aoffA;
                ldm4(ah[mt], base);
                ldm4(al[mt], base + 10240);
            }
            #pragma unroll
            for (int np = 0; np < 4; np++) {
                uint32_t bbase = sb + bufo + 20480 + (uint32_t)((nbase_w + np * 16) * AB_PITCH) + kof + aoffB;
                uint32_t rh[4], rl[4];
                ldm4(rh, bbase);
                ldm4(rl, bbase + 20480);
                #pragma unroll
                for (int mt = 0; mt < 2; mt++) {
                    mma_bf16(acc[mt][np * 2 + 0], ah[mt], rh + 0);
                    mma_bf16(acc[mt][np * 2 + 0], ah[mt], rl + 0);
                    mma_bf16(acc[mt][np * 2 + 0], al[mt], rh + 0);
                    mma_bf16(acc[mt][np * 2 + 1], ah[mt], rh + 2);
                    mma_bf16(acc[mt][np * 2 + 1], ah[mt], rl + 2);
                    mma_bf16(acc[mt][np * 2 + 1], al[mt], rh + 2);
                }
            }
        }

        if (more) CP_WAIT0();
        __syncthreads();
    }

    int g = lane >> 2, t2 = (lane & 3) * 2;
    #pragma unroll
    for (int nt = 0; nt < 8; nt++) {
        int c = nbase_w + nt * 8 + t2;
        float b0 = __ldg(&bias[c]), b1 = __ldg(&bias[c + 1]);
        float s0 = 0.f, s1 = 0.f, q0 = 0.f, q1 = 0.f;
        #pragma unroll
        for (int mt = 0; mt < 2; mt++) {
            int r0 = bm0 + mbase_w + mt * 16 + g;
            int r1 = r0 + 8;
            if (r0 < M) {
                float v0 = acc[mt][nt][0] + b0, v1 = acc[mt][nt][1] + b1;
                *(float2*)(C + (size_t)r0 * DD + c) = make_float2(v0, v1);
                if (STATS) { s0 += v0; q0 += v0 * v0; s1 += v1; q1 += v1 * v1; }
            }
            if (r1 < M) {
                float v0 = acc[mt][nt][2] + b0, v1 = acc[mt][nt][3] + b1;
                *(float2*)(C + (size_t)r1 * DD + c) = make_float2(v0, v1);
                if (STATS) { s0 += v0; q0 += v0 * v0; s1 += v1; q1 += v1 * v1; }
            }
        }
        if (STATS) {
            #pragma unroll
            for (int o = 4; o <= 16; o <<= 1) {
                s0 += __shfl_xor_sync(0xffffffffu, s0, o);
                s1 += __shfl_xor_sync(0xffffffffu, s1, o);
                q0 += __shfl_xor_sync(0xffffffffu, q0, o);
                q1 += __shfl_xor_sync(0xffffffffu, q1, o);
            }
            if (g == 0) {
                atomicAdd(&g_bns[c], s0);
                atomicAdd(&g_bns[c + 1], s1);
                atomicAdd(&g_bnq[c], q0);
                atomicAdd(&g_bnq[c + 1], q1);
            }
        }
    }
}

// ---------------- BatchNorm + ELU ----------------
__global__ void k_zero_bn() {
    int c = threadIdx.x;
    g_bns[c] = 0.f;
    g_bnq[c] = 0.f;
}
__global__ void k_bn_apply(float* __restrict__ X,
                           const float* __restrict__ gamma,
                           const float* __restrict__ beta) {
    int idx = blockIdx.x * 256 + threadIdx.x;
    if (idx >= NN * (DD / 4)) return;
    int c4 = idx & 63;
    int c = c4 * 4;
    const float invN = 1.f / (float)NN;
    float4 sm = *(const float4*)&g_bns[c];
    float4 sq = *(const float4*)&g_bnq[c];
    float4 gm = *(const float4*)&gamma[c];
    float4 bt = *(const float4*)&beta[c];
    float mu, var, sc;
    float4 x = ((float4*)X)[idx];
    float4 y;
    mu = sm.x * invN; var = sq.x * invN - mu * mu; sc = gm.x * rsqrtf(var + 1e-5f);
    y.x = sc * (x.x - mu) + bt.x;
    mu = sm.y * invN; var = sq.y * invN - mu * mu; sc = gm.y * rsqrtf(var + 1e-5f);
    y.y = sc * (x.y - mu) + bt.y;
    mu = sm.z * invN; var = sq.z * invN - mu * mu; sc = gm.z * rsqrtf(var + 1e-5f);
    y.z = sc * (x.z - mu) + bt.z;
    mu = sm.w * invN; var = sq.w * invN - mu * mu; sc = gm.w * rsqrtf(var + 1e-5f);
    y.w = sc * (x.w - mu) + bt.w;
    y.x = (y.x > 0.f) ? y.x : (__expf(y.x) - 1.f);
    y.y = (y.y > 0.f) ? y.y : (__expf(y.y) - 1.f);
    y.z = (y.z > 0.f) ? y.z : (__expf(y.z) - 1.f);
    y.w = (y.w > 0.f) ? y.w : (__expf(y.w) - 1.f);
    ((float4*)X)[idx] = y;
}

// ---------------- logits GEMM ----------------
__global__ __launch_bounds__(320) void k_logits(
    const float* __restrict__ X, const float* __restrict__ W,
    const float* __restrict__ bias, float* __restrict__ O, int M)
{
    __shared__ float Xs[32][68];
    __shared__ float Ws[32][40];
    int tid = threadIdx.x;
    int bm0 = blockIdx.x * 64;
    int rg = tid / 40;
    int col = tid % 40;
    float acc[8];
    #pragma unroll
    for (int i = 0; i < 8; i++) acc[i] = 0.f;

    for (int k0 = 0; k0 < DD; k0 += 32) {
        for (int idx = tid; idx < 512; idx += 320) {
            int row = idx >> 3;
            int kq = idx & 7;
            float4 v = make_float4(0.f, 0.f, 0.f, 0.f);
            int gr = bm0 + row;
            if (gr < M) v = *(const float4*)(X + (size_t)gr * DD + k0 + kq * 4);
            Xs[kq * 4 + 0][row] = v.x;
            Xs[kq * 4 + 1][row] = v.y;
            Xs[kq * 4 + 2][row] = v.z;
            Xs[kq * 4 + 3][row] = v.w;
        }
        for (int idx = tid; idx < 1280; idx += 320) {
            int k = idx / 40, c = idx % 40;
            Ws[k][c] = W[(size_t)(k0 + k) * CC + c];
        }
        __syncthreads();
        #pragma unroll
        for (int kk = 0; kk < 32; kk++) {
            float w = Ws[kk][col];
            float a0[4], a1[4];
            *(float4*)&a0[0] = *(float4*)&Xs[kk][rg * 8];
            *(float4*)&a1[0] = *(float4*)&Xs[kk][rg * 8 + 4];
            acc[0] += a0[0] * w; acc[1] += a0[1] * w;
            acc[2] += a0[2] * w; acc[3] += a0[3] * w;
            acc[4] += a1[0] * w; acc[5] += a1[1] * w;
            acc[6] += a1[2] * w; acc[7] += a1[3] * w;
        }
        __syncthreads();
    }
    float b = bias[col];
    #pragma unroll
    for (int i = 0; i < 8; i++) {
        int r = bm0 + rg * 8 + i;
        if (r < M) O[(size_t)r * CC + col] = acc[i] + b;
    }
}

// ---------------- static stream/event init ----------------
struct SideRes {
    cudaStream_t sB;
    cudaEvent_t evFork, evJoin;
    SideRes() {
        cudaStreamCreateWithFlags(&sB, cudaStreamNonBlocking);
        cudaEventCreateWithFlags(&evFork, cudaEventDisableTiming);
        cudaEventCreateWithFlags(&evJoin, cudaEventDisableTiming);
        cudaFuncSetAttribute(hmma_gemm_fc, cudaFuncAttributeMaxDynamicSharedMemorySize, SMEM_GEMM);
        cudaFuncSetAttribute(hmma_gemm_pk<true>,  cudaFuncAttributeMaxDynamicSharedMemorySize, SMEM_GEMM);
        cudaFuncSetAttribute(hmma_gemm_pk<false>, cudaFuncAttributeMaxDynamicSharedMemorySize, SMEM_GEMM);
    }
};
static SideRes g_sr;

// ---------------- driver ----------------
extern "C" void kernel_launch(void* const* d_in, const int* in_sizes, int n_in,
                              void* d_out, int out_size)
{
    const float* feat  = (const float*)d_in[0];
    const int*   src   = (const int*)d_in[1];
    const int*   dst   = (const int*)d_in[2];
    const float* W_fc  = (const float*)d_in[3];
    const float* b_fc  = (const float*)d_in[4];
    const float* W1    = (const float*)d_in[5];
    const float* b1    = (const float*)d_in[6];
    const float* W2    = (const float*)d_in[7];
    const float* b2    = (const float*)d_in[8];
    const float* W3    = (const float*)d_in[9];
    const float* b3    = (const float*)d_in[10];
    const float* gamma = (const float*)d_in[11];
    const float* beta  = (const float*)d_in[12];
    const float* W_lin = (const float*)d_in[13];
    const float* b_lin = (const float*)d_in[14];
    float* out = (float*)d_out;

    float* gX;  cudaGetSymbolAddress((void**)&gX, g_X);
    unsigned char *gAh, *gAl;
    cudaGetSymbolAddress((void**)&gAh, g_Ah);
    cudaGetSymbolAddress((void**)&gAl, g_Al);
    unsigned char *pFh, *pFl, *p1h, *p1l, *p2h, *p2l, *p3h, *p3l;
    cudaGetSymbolAddress((void**)&pFh, g_Wfc_h);
    cudaGetSymbolAddress((void**)&pFl, g_Wfc_l);
    cudaGetSymbolAddress((void**)&p1h, g_W1_h);
    cudaGetSymbolAddress((void**)&p1l, g_W1_l);
    cudaGetSymbolAddress((void**)&p2h, g_W2_h);
    cudaGetSymbolAddress((void**)&p2l, g_W2_l);
    cudaGetSymbolAddress((void**)&p3h, g_W3_h);
    cudaGetSymbolAddress((void**)&p3l, g_W3_l);

    const int NB_N = (NN + 255) / 256;
    const int NB_E = (EE + 255) / 256;
    const int GEMM_GRID = (NN + 127) / 128;  // 391
    dim3 spmm_block(32, 8);
    int spmm_grid = (NN + 7) / 8;
    int bn_grid = (NN * (DD / 4) + 255) / 256;

    // fork: side stream does graph prep + layer-weight prepack + bn zero
    cudaEventRecord(g_sr.evFork, 0);
    cudaStreamWaitEvent(g_sr.sB, g_sr.evFork, 0);

    k_zero_prep<<<NB_N, 256, 0, g_sr.sB>>>();
    k_count<<<NB_E, 256, 0, g_sr.sB>>>(src, dst);
    k_norms<<<NB_N, 256, 0, g_sr.sB>>>();
    k_scan1<<<49, 1024, 0, g_sr.sB>>>();
    k_scan2<<<1, 64, 0, g_sr.sB>>>();
    k_scan3<<<NB_N, 256, 0, g_sr.sB>>>();
    k_fill<<<NB_E, 256, 0, g_sr.sB>>>(src, dst);
    k_prepack<<<(DD * (DD / 8) + 255) / 256, 256, 0, g_sr.sB>>>(W1, p1h, p1l, DD);
    k_prepack<<<(DD * (DD / 8) + 255) / 256, 256, 0, g_sr.sB>>>(W2, p2h, p2l, DD);
    k_prepack<<<(DD * (DD / 8) + 255) / 256, 256, 0, g_sr.sB>>>(W3, p3h, p3l, DD);
    k_zero_bn<<<1, 256, 0, g_sr.sB>>>();
    cudaEventRecord(g_sr.evJoin, g_sr.sB);

    // main stream: fc prepack + fc GEMM (bf16 3-product — R5 known-good config)
    k_prepack<<<(DD * (FF / 8) + 255) / 256, 256>>>(W_fc, pFh, pFl, FF);
    hmma_gemm_fc<<<GEMM_GRID, 512, SMEM_GEMM>>>(feat, pFh, pFl, b_fc, gX, NN, FF);

    // join
    cudaStreamWaitEvent(0, g_sr.evJoin, 0);

    // layer 1 (stats fused into GEMM epilogue)
    k_spmm<<<spmm_grid, spmm_block>>>(gX);
    hmma_gemm_pk<true><<<GEMM_GRID, 512, SMEM_GEMM>>>(gAh, gAl, p1h, p1l, b1, gX, NN);
    k_bn_apply<<<bn_grid, 256>>>(gX, gamma, beta);
    k_zero_bn<<<1, 256>>>();

    // layer 2 (stats fused)
    k_spmm<<<spmm_grid, spmm_block>>>(gX);
    hmma_gemm_pk<true><<<GEMM_GRID, 512, SMEM_GEMM>>>(gAh, gAl, p2h, p2l, b2, gX, NN);
    k_bn_apply<<<bn_grid, 256>>>(gX, gamma, beta);

    // layer 3 -> features into d_out[0 : N*D)
    k_spmm<<<spmm_grid, spmm_block>>>(gX);
    hmma_gemm_pk<false><<<GEMM_GRID, 512, SMEM_GEMM>>>(gAh, gAl, p3h, p3l, b3, out, NN);

    // logits -> d_out[N*D : )
    k_logits<<<(NN + 63) / 64, 320>>>(out, W_lin, b_lin, out + (size_t)NN * DD, NN);
}

// round 10
// speedup vs baseline: 1.3308x; 1.0159x over previous
#include <cuda_runtime.h>
#include <cuda_bf16.h>
#include <math.h>
#include <stdint.h>

#define NN 50000
#define EE 300000
#define DD 256
#define FF 1024
#define CC 40
#define AB_PITCH 80

// ---------------- scratch (static device globals; no allocation) ----------------
__device__ float g_X[NN * DD];
__device__ float g_ns[NN];
__device__ float g_nd[NN];
__device__ int   g_degout[NN];
__device__ int   g_degin[NN];
__device__ int   g_fill[NN];
__device__ int   g_incl[49 * 1024];
__device__ int   g_bsum[64];
__device__ int   g_boff[64];
__device__ int   g_rowptr[NN + 1];
__device__ int   g_col[EE];
__device__ float g_bns[DD];
__device__ float g_bnq[DD];

// packed split-bf16 A planes written by spmm: per (rowblk, ktile): 128 rows x 80B
__device__ __align__(16) unsigned char g_Ah[391 * 8 * 10240];
__device__ __align__(16) unsigned char g_Al[391 * 8 * 10240];

// prepacked weights: per ktile: 256 n-rows x 80B = 20480 B (bf16 hi/lo planes)
__device__ __align__(16) unsigned char g_Wfc_h[32 * 20480];
__device__ __align__(16) unsigned char g_Wfc_l[32 * 20480];
__device__ __align__(16) unsigned char g_W1_h[8 * 20480];
__device__ __align__(16) unsigned char g_W1_l[8 * 20480];
__device__ __align__(16) unsigned char g_W2_h[8 * 20480];
__device__ __align__(16) unsigned char g_W2_l[8 * 20480];
__device__ __align__(16) unsigned char g_W3_h[8 * 20480];
__device__ __align__(16) unsigned char g_W3_l[8 * 20480];

// ================= helpers =================
__device__ __forceinline__ uint32_t smem_to_u32(const void* p) {
    uint32_t a;
    asm("{ .reg .u64 t; cvta.to.shared.u64 t, %1; cvt.u32.u64 %0, t; }" : "=r"(a) : "l"(p));
    return a;
}
__device__ __forceinline__ void ldm4(uint32_t* r, uint32_t addr) {
    asm volatile("ldmatrix.sync.aligned.m8n8.x4.shared.b16 {%0,%1,%2,%3}, [%4];"
        : "=r"(r[0]), "=r"(r[1]), "=r"(r[2]), "=r"(r[3]) : "r"(addr));
}
__device__ __forceinline__ void mma_bf16(float* d, const uint32_t* a, const uint32_t* b) {
    asm volatile(
        "mma.sync.aligned.m16n8k16.row.col.f32.bf16.bf16.f32 "
        "{%0,%1,%2,%3}, {%4,%5,%6,%7}, {%8,%9}, {%0,%1,%2,%3};"
        : "+f"(d[0]), "+f"(d[1]), "+f"(d[2]), "+f"(d[3])
        : "r"(a[0]), "r"(a[1]), "r"(a[2]), "r"(a[3]), "r"(b[0]), "r"(b[1]));
}
__device__ __forceinline__ void cp16(uint32_t saddr, const void* gaddr) {
    asm volatile("cp.async.cg.shared.global [%0], [%1], 16;" :: "r"(saddr), "l"(gaddr));
}
#define CP_COMMIT() asm volatile("cp.async.commit_group;" ::: "memory")
#define CP_WAIT0()  asm volatile("cp.async.wait_group 0;" ::: "memory")

__device__ __forceinline__ void split2(float x0, float x1, uint32_t& ph, uint32_t& pl) {
    __nv_bfloat16 h0 = __float2bfloat16(x0), h1 = __float2bfloat16(x1);
    float r0 = x0 - __bfloat162float(h0), r1 = x1 - __bfloat162float(h1);
    __nv_bfloat16 l0 = __float2bfloat16(r0), l1 = __float2bfloat16(r1);
    ph = ((uint32_t)__bfloat16_as_ushort(h1) << 16) | (uint32_t)__bfloat16_as_ushort(h0);
    pl = ((uint32_t)__bfloat16_as_ushort(l1) << 16) | (uint32_t)__bfloat16_as_ushort(l0);
}

// FMA-pipe exp for x <= 0 (magic-number exp2 + degree-5 Taylor of 2^f)
__device__ __forceinline__ float fexp_neg(float x) {
    float z = fmaxf(x * 1.44269504f, -126.0f);
    float t = z + 12582912.0f;              // round(z) via magic
    float n = t - 12582912.0f;
    float f = z - n;                        // [-0.5, 0.5]
    int   i = __float_as_int(t);
    float p = 1.3333558146e-3f;
    p = fmaf(p, f, 9.6181291076e-3f);
    p = fmaf(p, f, 5.5504108664e-2f);
    p = fmaf(p, f, 2.4022650696e-1f);
    p = fmaf(p, f, 6.9314718056e-1f);
    p = fmaf(p, f, 1.0f);
    float s = __int_as_float((((i & 0x7FFFFF) - 0x400000 + 127) << 23));
    return p * s;
}

// ---------------- graph prep ----------------
__global__ void k_zero_prep() {
    int i = blockIdx.x * 256 + threadIdx.x;
    if (i < NN) { g_degout[i] = 0; g_degin[i] = 0; g_fill[i] = 0; }
}
__global__ void k_count(const int* __restrict__ src, const int* __restrict__ dst) {
    int e = blockIdx.x * 256 + threadIdx.x;
    if (e < EE) { atomicAdd(&g_degout[src[e]], 1); atomicAdd(&g_degin[dst[e]], 1); }
}
__global__ void k_norms() {
    int i = blockIdx.x * 256 + threadIdx.x;
    if (i < NN) {
        g_ns[i] = rsqrtf((float)max(g_degout[i], 1));
        g_nd[i] = rsqrtf((float)max(g_degin[i], 1));
    }
}
__global__ void k_scan1() {
    __shared__ int s[1024];
    int tid = threadIdx.x;
    int i = blockIdx.x * 1024 + tid;
    int v = (i < NN) ? g_degin[i] : 0;
    s[tid] = v;
    __syncthreads();
    for (int off = 1; off < 1024; off <<= 1) {
        int t = (tid >= off) ? s[tid - off] : 0;
        __syncthreads(); s[tid] += t; __syncthreads();
    }
    g_incl[i] = s[tid];
    if (tid == 1023) g_bsum[blockIdx.x] = s[1023];
}
__global__ void k_scan2() {
    __shared__ int s[64];
    int tid = threadIdx.x;
    int v = (tid < 49) ? g_bsum[tid] : 0;
    s[tid] = v;
    __syncthreads();
    for (int off = 1; off < 64; off <<= 1) {
        int t = (tid >= off) ? s[tid - off] : 0;
        __syncthreads(); s[tid] += t; __syncthreads();
    }
    g_boff[tid] = s[tid] - v;
}
__global__ void k_scan3() {
    int i = blockIdx.x * 256 + threadIdx.x;
    if (i < NN) g_rowptr[i + 1] = g_incl[i] + g_boff[i >> 10];
    if (i == 0) g_rowptr[0] = 0;
}
__global__ void k_fill(const int* __restrict__ src, const int* __restrict__ dst) {
    int e = blockIdx.x * 256 + threadIdx.x;
    if (e < EE) {
        int d = dst[e];
        int pos = g_rowptr[d] + atomicAdd(&g_fill[d], 1);
        g_col[pos] = src[e];
    }
}

// ---------------- SpMM gather -> packed split-bf16 planes (norm_d fused) ----------------
__global__ void k_spmm(const float* __restrict__ X) {
    int node = blockIdx.x * 8 + threadIdx.y;
    if (node >= NN) return;
    int lane = threadIdx.x;
    float4 a0 = make_float4(0.f, 0.f, 0.f, 0.f);
    float4 a1 = make_float4(0.f, 0.f, 0.f, 0.f);
    int beg = g_rowptr[node], end = g_rowptr[node + 1];
    for (int e = beg; e < end; e++) {
        int s = g_col[e];
        float w = g_ns[s];
        const float4* row = (const float4*)(X + (size_t)s * DD);
        float4 v = row[lane];
        a0.x += w * v.x; a0.y += w * v.y; a0.z += w * v.z; a0.w += w * v.w;
        v = row[lane + 32];
        a1.x += w * v.x; a1.y += w * v.y; a1.z += w * v.z; a1.w += w * v.w;
    }
    float nd = g_nd[node];
    a0.x *= nd; a0.y *= nd; a0.z *= nd; a0.w *= nd;
    a1.x *= nd; a1.y *= nd; a1.z *= nd; a1.w *= nd;

    int kt = lane >> 3;
    size_t rb = (size_t)(node >> 7) * 8;
    uint32_t roff = (uint32_t)((node & 127) * AB_PITCH + (lane & 7) * 8);
    uint32_t h0, l0, h1, l1;

    split2(a0.x, a0.y, h0, l0);
    split2(a0.z, a0.w, h1, l1);
    size_t base = (rb + kt) * 10240 + roff;
    *(uint2*)(g_Ah + base) = make_uint2(h0, h1);
    *(uint2*)(g_Al + base) = make_uint2(l0, l1);

    split2(a1.x, a1.y, h0, l0);
    split2(a1.z, a1.w, h1, l1);
    base = (rb + 4 + kt) * 10240 + roff;
    *(uint2*)(g_Ah + base) = make_uint2(h0, h1);
    *(uint2*)(g_Al + base) = make_uint2(l0, l1);
}

// ---------------- weight prepack (bf16 split) ----------------
__global__ void k_prepack(const float* __restrict__ W, unsigned char* __restrict__ ph,
                          unsigned char* __restrict__ pl, int K) {
    int task = blockIdx.x * 256 + threadIdx.x;
    int nk8 = K >> 3;
    if (task >= DD * nk8) return;
    int n = task / nk8, k8 = task % nk8;
    int k0 = k8 << 3;
    float x[8];
    #pragma unroll
    for (int i = 0; i < 8; i++) x[i] = W[(size_t)(k0 + i) * DD + n];
    uint4 vh, vl;
    split2(x[0], x[1], vh.x, vl.x);
    split2(x[2], x[3], vh.y, vl.y);
    split2(x[4], x[5], vh.z, vl.z);
    split2(x[6], x[7], vh.w, vl.w);
    size_t off = (size_t)(k0 >> 5) * 20480 + (size_t)n * AB_PITCH + (k0 & 31) * 2;
    *(uint4*)(ph + off) = vh;
    *(uint4*)(pl + off) = vl;
}

// ================= merged-N HMMA GEMM cores (bf16 3-product) =================
// CTA 128x256, 512 thr, warps 4x4, warp tile 32x64
// smem buffer 61440: Ah@0(10240) Al@10240 Bh@20480(20480) Bl@40960(20480); x2
#define SMEM_GEMM 122880

// ---- fc: fp32 A split on the fly ----
__global__ void __launch_bounds__(512) hmma_gemm_fc(
    const float* __restrict__ A,
    const unsigned char* __restrict__ Bh_g, const unsigned char* __restrict__ Bl_g,
    const float* __restrict__ bias, float* __restrict__ C, int M, int K)
{
    extern __shared__ __align__(16) unsigned char smem[];
    uint32_t sb = smem_to_u32(smem);
    int tid = threadIdx.x;
    int wid = tid >> 5, lane = tid & 31;
    int bm0 = blockIdx.x * 128;
    int nIter = K >> 5;

    int arow = tid >> 2;
    int akq = (tid & 3) * 8;
    int agr = bm0 + arow;
    bool avalid = (agr < M);
    const float* aptr = A + (size_t)(avalid ? agr : 0) * K + akq;
    uint32_t a_soff = (uint32_t)(arow * AB_PITCH + akq * 2);

    int wr = wid >> 2, wc = wid & 3;
    int mbase_w = wr * 32;
    int nbase_w = wc * 64;

    int lj = lane >> 3, lr = lane & 7;
    uint32_t aoffA = (uint32_t)(((lj & 1) * 8 + lr) * AB_PITCH + (lj >> 1) * 16);
    uint32_t aoffB = (uint32_t)(((lj >> 1) * 8 + lr) * AB_PITCH + (lj & 1) * 16);

    float acc[2][8][4];
    #pragma unroll
    for (int mt = 0; mt < 2; mt++)
        #pragma unroll
        for (int nt = 0; nt < 8; nt++)
            #pragma unroll
            for (int i = 0; i < 4; i++) acc[mt][nt][i] = 0.f;

    {
        for (int c = tid; c < 1280; c += 512) {
            cp16(sb + 20480 + c * 16, Bh_g + c * 16);
            cp16(sb + 40960 + c * 16, Bl_g + c * 16);
        }
        CP_COMMIT();
        float4 v0 = make_float4(0.f, 0.f, 0.f, 0.f), v1 = v0;
        if (avalid) { v0 = *(const float4*)(aptr); v1 = *(const float4*)(aptr + 4); }
        uint4 vh, vl;
        split2(v0.x, v0.y, vh.x, vl.x);
        split2(v0.z, v0.w, vh.y, vl.y);
        split2(v1.x, v1.y, vh.z, vl.z);
        split2(v1.z, v1.w, vh.w, vl.w);
        *(uint4*)(smem + a_soff) = vh;
        *(uint4*)(smem + 10240 + a_soff) = vl;
        CP_WAIT0();
        __syncthreads();
    }

    for (int it = 0; it < nIter; it++) {
        uint32_t bufo = (uint32_t)((it & 1) * 61440);
        uint32_t nbufo = (uint32_t)(((it + 1) & 1) * 61440);
        bool more = (it + 1 < nIter);

        float4 v0 = make_float4(0.f, 0.f, 0.f, 0.f), v1 = v0;
        if (more) {
            size_t tb = (size_t)(it + 1) * 20480;
            for (int c = tid; c < 1280; c += 512) {
                cp16(sb + nbufo + 20480 + c * 16, Bh_g + tb + c * 16);
                cp16(sb + nbufo + 40960 + c * 16, Bl_g + tb + c * 16);
            }
            CP_COMMIT();
            if (avalid) {
                int k0 = (it + 1) << 5;
                v0 = *(const float4*)(aptr + k0);
                v1 = *(const float4*)(aptr + k0 + 4);
            }
        }

        #pragma unroll
        for (int ks = 0; ks < 2; ks++) {
            uint32_t kof = (uint32_t)(ks * 32);
            uint32_t ah[2][4], al[2][4];
            #pragma unroll
            for (int mt = 0; mt < 2; mt++) {
                uint32_t base = sb + bufo + (uint32_t)((mbase_w + mt * 16) * AB_PITCH) + kof + aoffA;
                ldm4(ah[mt], base);
                ldm4(al[mt], base + 10240);
            }
            #pragma unroll
            for (int np = 0; np < 4; np++) {
                uint32_t bbase = sb + bufo + 20480 + (uint32_t)((nbase_w + np * 16) * AB_PITCH) + kof + aoffB;
                uint32_t rh[4], rl[4];
                ldm4(rh, bbase);
                ldm4(rl, bbase + 20480);
                #pragma unroll
                for (int mt = 0; mt < 2; mt++) {
                    mma_bf16(acc[mt][np * 2 + 0], ah[mt], rh + 0);
                    mma_bf16(acc[mt][np * 2 + 0], ah[mt], rl + 0);
                    mma_bf16(acc[mt][np * 2 + 0], al[mt], rh + 0);
                    mma_bf16(acc[mt][np * 2 + 1], ah[mt], rh + 2);
                    mma_bf16(acc[mt][np * 2 + 1], ah[mt], rl + 2);
                    mma_bf16(acc[mt][np * 2 + 1], al[mt], rh + 2);
                }
            }
        }

        if (more) {
            uint4 vh, vl;
            split2(v0.x, v0.y, vh.x, vl.x);
            split2(v0.z, v0.w, vh.y, vl.y);
            split2(v1.x, v1.y, vh.z, vl.z);
            split2(v1.z, v1.w, vh.w, vl.w);
            *(uint4*)(smem + nbufo + a_soff) = vh;
            *(uint4*)(smem + nbufo + 10240 + a_soff) = vl;
            CP_WAIT0();
        }
        __syncthreads();
    }

    int g = lane >> 2, t2 = (lane & 3) * 2;
    #pragma unroll
    for (int mt = 0; mt < 2; mt++) {
        int r0 = bm0 + mbase_w + mt * 16 + g;
        int r1 = r0 + 8;
        #pragma unroll
        for (int nt = 0; nt < 8; nt++) {
            int c = nbase_w + nt * 8 + t2;
            float b0 = __ldg(&bias[c]), b1 = __ldg(&bias[c + 1]);
            if (r0 < M) *(float2*)(C + (size_t)r0 * DD + c) =
                make_float2(acc[mt][nt][0] + b0, acc[mt][nt][1] + b1);
            if (r1 < M) *(float2*)(C + (size_t)r1 * DD + c) =
                make_float2(acc[mt][nt][2] + b0, acc[mt][nt][3] + b1);
        }
    }
}

// ---- layer GEMM: packed split-bf16 A ----
__global__ void __launch_bounds__(512) hmma_gemm_pk(
    const unsigned char* __restrict__ Ah_g, const unsigned char* __restrict__ Al_g,
    const unsigned char* __restrict__ Bh_g, const unsigned char* __restrict__ Bl_g,
    const float* __restrict__ bias, float* __restrict__ C, int M)
{
    extern __shared__ __align__(16) unsigned char smem[];
    uint32_t sb = smem_to_u32(smem);
    int tid = threadIdx.x;
    int wid = tid >> 5, lane = tid & 31;
    int bm0 = blockIdx.x * 128;
    const int nIter = 8;
    size_t abase = (size_t)blockIdx.x * 8 * 10240;

    int wr = wid >> 2, wc = wid & 3;
    int mbase_w = wr * 32;
    int nbase_w = wc * 64;

    int lj = lane >> 3, lr = lane & 7;
    uint32_t aoffA = (uint32_t)(((lj & 1) * 8 + lr) * AB_PITCH + (lj >> 1) * 16);
    uint32_t aoffB = (uint32_t)(((lj >> 1) * 8 + lr) * AB_PITCH + (lj & 1) * 16);

    float acc[2][8][4];
    #pragma unroll
    for (int mt = 0; mt < 2; mt++)
        #pragma unroll
        for (int nt = 0; nt < 8; nt++)
            #pragma unroll
            for (int i = 0; i < 4; i++) acc[mt][nt][i] = 0.f;

    {
        for (int c = tid; c < 640; c += 512) {
            cp16(sb + c * 16, Ah_g + abase + c * 16);
            cp16(sb + 10240 + c * 16, Al_g + abase + c * 16);
        }
        for (int c = tid; c < 1280; c += 512) {
            cp16(sb + 20480 + c * 16, Bh_g + c * 16);
            cp16(sb + 40960 + c * 16, Bl_g + c * 16);
        }
        CP_COMMIT();
        CP_WAIT0();
        __syncthreads();
    }

    for (int it = 0; it < nIter; it++) {
        uint32_t bufo = (uint32_t)((it & 1) * 61440);
        uint32_t nbufo = (uint32_t)(((it + 1) & 1) * 61440);
        bool more = (it + 1 < nIter);

        if (more) {
            size_t ta = abase + (size_t)(it + 1) * 10240;
            size_t tb = (size_t)(it + 1) * 20480;
            for (int c = tid; c < 640; c += 512) {
                cp16(sb + nbufo + c * 16, Ah_g + ta + c * 16);
                cp16(sb + nbufo + 10240 + c * 16, Al_g + ta + c * 16);
            }
            for (int c = tid; c < 1280; c += 512) {
                cp16(sb + nbufo + 20480 + c * 16, Bh_g + tb + c * 16);
                cp16(sb + nbufo + 40960 + c * 16, Bl_g + tb + c * 16);
            }
            CP_COMMIT();
        }

        #pragma unroll
        for (int ks = 0; ks < 2; ks++) {
            uint32_t kof = (uint32_t)(ks * 32);
            uint32_t ah[2][4], al[2][4];
            #pragma unroll
            for (int mt = 0; mt < 2; mt++) {
                uint32_t base = sb + bufo + (uint32_t)((mbase_w + mt * 16) * AB_PITCH) + kof + aoffA;
                ldm4(ah[mt], base);
                ldm4(al[mt], base + 10240);
            }
            #pragma unroll
            for (int np = 0; np < 4; np++) {
                uint32_t bbase = sb + bufo + 20480 + (uint32_t)((nbase_w + np * 16) * AB_PITCH) + kof + aoffB;
                uint32_t rh[4], rl[4];
                ldm4(rh, bbase);
                ldm4(rl, bbase + 20480);
                #pragma unroll
                for (int mt = 0; mt < 2; mt++) {
                    mma_bf16(acc[mt][np * 2 + 0], ah[mt], rh + 0);
                    mma_bf16(acc[mt][np * 2 + 0], ah[mt], rl + 0);
                    mma_bf16(acc[mt][np * 2 + 0], al[mt], rh + 0);
                    mma_bf16(acc[mt][np * 2 + 1], ah[mt], rh + 2);
                    mma_bf16(acc[mt][np * 2 + 1], ah[mt], rl + 2);
                    mma_bf16(acc[mt][np * 2 + 1], al[mt], rh + 2);
                }
            }
        }

        if (more) CP_WAIT0();
        __syncthreads();
    }

    int g = lane >> 2, t2 = (lane & 3) * 2;
    #pragma unroll
    for (int mt = 0; mt < 2; mt++) {
        int r0 = bm0 + mbase_w + mt * 16 + g;
        int r1 = r0 + 8;
        #pragma unroll
        for (int nt = 0; nt < 8; nt++) {
            int c = nbase_w + nt * 8 + t2;
            float b0 = __ldg(&bias[c]), b1 = __ldg(&bias[c + 1]);
            if (r0 < M) *(float2*)(C + (size_t)r0 * DD + c) =
                make_float2(acc[mt][nt][0] + b0, acc[mt][nt][1] + b1);
            if (r1 < M) *(float2*)(C + (size_t)r1 * DD + c) =
                make_float2(acc[mt][nt][2] + b0, acc[mt][nt][3] + b1);
        }
    }
}

// ---------------- BatchNorm + ELU ----------------
__global__ void k_zero_bn() {
    int c = threadIdx.x;
    g_bns[c] = 0.f;
    g_bnq[c] = 0.f;
}
__global__ void k_bn_stats(const float* __restrict__ X) {
    int c = threadIdx.x;
    int r0 = blockIdx.x * 256;
    int r1 = min(r0 + 256, NN);
    float s = 0.f, q = 0.f;
    for (int r = r0; r < r1; r++) {
        float v = X[(size_t)r * DD + c];
        s += v; q += v * v;
    }
    atomicAdd(&g_bns[c], s);
    atomicAdd(&g_bnq[c], q);
}
__global__ void k_bn_apply(float* __restrict__ X,
                           const float* __restrict__ gamma,
                           const float* __restrict__ beta) {
    int idx = blockIdx.x * 256 + threadIdx.x;
    if (idx >= NN * (DD / 4)) return;
    int c4 = idx & 63;
    int c = c4 * 4;
    const float invN = 1.f / (float)NN;
    float4 sm = *(const float4*)&g_bns[c];
    float4 sq = *(const float4*)&g_bnq[c];
    float4 gm = *(const float4*)&gamma[c];
    float4 bt = *(const float4*)&beta[c];
    float mu, var, sc;
    float4 x = ((float4*)X)[idx];
    float4 y;
    mu = sm.x * invN; var = sq.x * invN - mu * mu; sc = gm.x * rsqrtf(var + 1e-5f);
    y.x = sc * (x.x - mu) + bt.x;
    mu = sm.y * invN; var = sq.y * invN - mu * mu; sc = gm.y * rsqrtf(var + 1e-5f);
    y.y = sc * (x.y - mu) + bt.y;
    mu = sm.z * invN; var = sq.z * invN - mu * mu; sc = gm.z * rsqrtf(var + 1e-5f);
    y.z = sc * (x.z - mu) + bt.z;
    mu = sm.w * invN; var = sq.w * invN - mu * mu; sc = gm.w * rsqrtf(var + 1e-5f);
    y.w = sc * (x.w - mu) + bt.w;
    // hybrid ELU: .x/.z on MUFU, .y/.w on FMA-pipe polynomial (pipe load balance)
    y.x = (y.x > 0.f) ? y.x : (__expf(y.x) - 1.f);
    y.y = (y.y > 0.f) ? y.y : (fexp_neg(y.y) - 1.f);
    y.z = (y.z > 0.f) ? y.z : (__expf(y.z) - 1.f);
    y.w = (y.w > 0.f) ? y.w : (fexp_neg(y.w) - 1.f);
    ((float4*)X)[idx] = y;
}

// ---------------- logits GEMM ----------------
__global__ __launch_bounds__(320) void k_logits(
    const float* __restrict__ X, const float* __restrict__ W,
    const float* __restrict__ bias, float* __restrict__ O, int M)
{
    __shared__ float Xs[32][68];
    __shared__ float Ws[32][40];
    int tid = threadIdx.x;
    int bm0 = blockIdx.x * 64;
    int rg = tid / 40;
    int col = tid % 40;
    float acc[8];
    #pragma unroll
    for (int i = 0; i < 8; i++) acc[i] = 0.f;

    for (int k0 = 0; k0 < DD; k0 += 32) {
        for (int idx = tid; idx < 512; idx += 320) {
            int row = idx >> 3;
            int kq = idx & 7;
            float4 v = make_float4(0.f, 0.f, 0.f, 0.f);
            int gr = bm0 + row;
            if (gr < M) v = *(const float4*)(X + (size_t)gr * DD + k0 + kq * 4);
            Xs[kq * 4 + 0][row] = v.x;
            Xs[kq * 4 + 1][row] = v.y;
            Xs[kq * 4 + 2][row] = v.z;
            Xs[kq * 4 + 3][row] = v.w;
        }
        for (int idx = tid; idx < 1280; idx += 320) {
            int k = idx / 40, c = idx % 40;
            Ws[k][c] = W[(size_t)(k0 + k) * CC + c];
        }
        __syncthreads();
        #pragma unroll
        for (int kk = 0; kk < 32; kk++) {
            float w = Ws[kk][col];
            float a0[4], a1[4];
            *(float4*)&a0[0] = *(float4*)&Xs[kk][rg * 8];
            *(float4*)&a1[0] = *(float4*)&Xs[kk][rg * 8 + 4];
            acc[0] += a0[0] * w; acc[1] += a0[1] * w;
            acc[2] += a0[2] * w; acc[3] += a0[3] * w;
            acc[4] += a1[0] * w; acc[5] += a1[1] * w;
            acc[6] += a1[2] * w; acc[7] += a1[3] * w;
        }
        __syncthreads();
    }
    float b = bias[col];
    #pragma unroll
    for (int i = 0; i < 8; i++) {
        int r = bm0 + rg * 8 + i;
        if (r < M) O[(size_t)r * CC + col] = acc[i] + b;
    }
}

// ---------------- static stream/event init ----------------
struct SideRes {
    cudaStream_t sB;
    cudaEvent_t evFork, evJoin;
    SideRes() {
        cudaStreamCreateWithFlags(&sB, cudaStreamNonBlocking);
        cudaEventCreateWithFlags(&evFork, cudaEventDisableTiming);
        cudaEventCreateWithFlags(&evJoin, cudaEventDisableTiming);
        cudaFuncSetAttribute(hmma_gemm_fc, cudaFuncAttributeMaxDynamicSharedMemorySize, SMEM_GEMM);
        cudaFuncSetAttribute(hmma_gemm_pk, cudaFuncAttributeMaxDynamicSharedMemorySize, SMEM_GEMM);
    }
};
static SideRes g_sr;

// ---------------- driver ----------------
extern "C" void kernel_launch(void* const* d_in, const int* in_sizes, int n_in,
                              void* d_out, int out_size)
{
    const float* feat  = (const float*)d_in[0];
    const int*   src   = (const int*)d_in[1];
    const int*   dst   = (const int*)d_in[2];
    const float* W_fc  = (const float*)d_in[3];
    const float* b_fc  = (const float*)d_in[4];
    const float* W1    = (const float*)d_in[5];
    const float* b1    = (const float*)d_in[6];
    const float* W2    = (const float*)d_in[7];
    const float* b2    = (const float*)d_in[8];
    const float* W3    = (const float*)d_in[9];
    const float* b3    = (const float*)d_in[10];
    const float* gamma = (const float*)d_in[11];
    const float* beta  = (const float*)d_in[12];
    const float* W_lin = (const float*)d_in[13];
    const float* b_lin = (const float*)d_in[14];
    float* out = (float*)d_out;

    float* gX;  cudaGetSymbolAddress((void**)&gX, g_X);
    unsigned char *gAh, *gAl;
    cudaGetSymbolAddress((void**)&gAh, g_Ah);
    cudaGetSymbolAddress((void**)&gAl, g_Al);
    unsigned char *pFh, *pFl, *p1h, *p1l, *p2h, *p2l, *p3h, *p3l;
    cudaGetSymbolAddress((void**)&pFh, g_Wfc_h);
    cudaGetSymbolAddress((void**)&pFl, g_Wfc_l);
    cudaGetSymbolAddress((void**)&p1h, g_W1_h);
    cudaGetSymbolAddress((void**)&p1l, g_W1_l);
    cudaGetSymbolAddress((void**)&p2h, g_W2_h);
    cudaGetSymbolAddress((void**)&p2l, g_W2_l);
    cudaGetSymbolAddress((void**)&p3h, g_W3_h);
    cudaGetSymbolAddress((void**)&p3l, g_W3_l);

    const int NB_N = (NN + 255) / 256;
    const int NB_E = (EE + 255) / 256;
    const int GEMM_GRID = (NN + 127) / 128;  // 391
    dim3 spmm_block(32, 8);
    int spmm_grid = (NN + 7) / 8;
    int bn_grid = (NN * (DD / 4) + 255) / 256;

    // fork
    cudaEventRecord(g_sr.evFork, 0);
    cudaStreamWaitEvent(g_sr.sB, g_sr.evFork, 0);

    // interleaved submission: put hmma_gemm_fc at the launch index ncu's
    // fixed -s 5 -c 1 window has been hitting (diagnostic; semantics unchanged)
    k_zero_prep<<<NB_N, 256, 0, g_sr.sB>>>();
    k_count<<<NB_E, 256, 0, g_sr.sB>>>(src, dst);
    k_prepack<<<(DD * (FF / 8) + 255) / 256, 256>>>(W_fc, pFh, pFl, FF);      // main
    hmma_gemm_fc<<<GEMM_GRID, 512, SMEM_GEMM>>>(feat, pFh, pFl, b_fc, gX, NN, FF);  // main
    k_norms<<<NB_N, 256, 0, g_sr.sB>>>();
    k_scan1<<<49, 1024, 0, g_sr.sB>>>();
    k_scan2<<<1, 64, 0, g_sr.sB>>>();
    k_scan3<<<NB_N, 256, 0, g_sr.sB>>>();
    k_fill<<<NB_E, 256, 0, g_sr.sB>>>(src, dst);
    k_prepack<<<(DD * (DD / 8) + 255) / 256, 256, 0, g_sr.sB>>>(W1, p1h, p1l, DD);
    k_prepack<<<(DD * (DD / 8) + 255) / 256, 256, 0, g_sr.sB>>>(W2, p2h, p2l, DD);
    k_prepack<<<(DD * (DD / 8) + 255) / 256, 256, 0, g_sr.sB>>>(W3, p3h, p3l, DD);
    k_zero_bn<<<1, 256, 0, g_sr.sB>>>();
    cudaEventRecord(g_sr.evJoin, g_sr.sB);

    // join
    cudaStreamWaitEvent(0, g_sr.evJoin, 0);

    // layer 1
    k_spmm<<<spmm_grid, spmm_block>>>(gX);
    hmma_gemm_pk<<<GEMM_GRID, 512, SMEM_GEMM>>>(gAh, gAl, p1h, p1l, b1, gX, NN);
    k_bn_stats<<<NB_N, 256>>>(gX);
    k_bn_apply<<<bn_grid, 256>>>(gX, gamma, beta);
    k_zero_bn<<<1, 256>>>();

    // layer 2
    k_spmm<<<spmm_grid, spmm_block>>>(gX);
    hmma_gemm_pk<<<GEMM_GRID, 512, SMEM_GEMM>>>(gAh, gAl, p2h, p2l, b2, gX, NN);
    k_bn_stats<<<NB_N, 256>>>(gX);
    k_bn_apply<<<bn_grid, 256>>>(gX, gamma, beta);

    // layer 3 -> features into d_out[0 : N*D)
    k_spmm<<<spmm_grid, spmm_block>>>(gX);
    hmma_gemm_pk<<<GEMM_GRID, 512, SMEM_GEMM>>>(gAh, gAl, p3h, p3l, b3, out, NN);

    // logits -> d_out[N*D : )
    k_logits<<<(NN + 63) / 64, 320>>>(out, W_lin, b_lin, out + (size_t)NN * DD, NN);
}

// round 11
// speedup vs baseline: 1.3504x; 1.0147x over previous
#include <cuda_runtime.h>
#include <cuda_bf16.h>
#include <math.h>
#include <stdint.h>

#define NN 50000
#define EE 300000
#define DD 256
#define FF 1024
#define CC 40
#define AB_PITCH 80

// ---------------- scratch (static device globals; no allocation) ----------------
__device__ float g_X[NN * DD];
__device__ float g_ns[NN];
__device__ float g_nd[NN];
__device__ int   g_degout[NN];
__device__ int   g_degin[NN];
__device__ int   g_fill[NN];
__device__ int   g_incl[49 * 1024];
__device__ int   g_bsum[64];
__device__ int   g_boff[64];
__device__ int   g_rowptr[NN + 1];
__device__ int   g_col[EE];
__device__ float g_bns[DD];
__device__ float g_bnq[DD];

// packed split-bf16 A planes written by spmm: per (rowblk, ktile): 128 rows x 80B
__device__ __align__(16) unsigned char g_Ah[391 * 8 * 10240];
__device__ __align__(16) unsigned char g_Al[391 * 8 * 10240];

// prepacked weights: per ktile: 256 n-rows x 80B = 20480 B (bf16 hi/lo planes)
__device__ __align__(16) unsigned char g_Wfc_h[32 * 20480];
__device__ __align__(16) unsigned char g_Wfc_l[32 * 20480];
__device__ __align__(16) unsigned char g_W1_h[8 * 20480];
__device__ __align__(16) unsigned char g_W1_l[8 * 20480];
__device__ __align__(16) unsigned char g_W2_h[8 * 20480];
__device__ __align__(16) unsigned char g_W2_l[8 * 20480];
__device__ __align__(16) unsigned char g_W3_h[8 * 20480];
__device__ __align__(16) unsigned char g_W3_l[8 * 20480];

// ================= helpers =================
__device__ __forceinline__ uint32_t smem_to_u32(const void* p) {
    uint32_t a;
    asm("{ .reg .u64 t; cvta.to.shared.u64 t, %1; cvt.u32.u64 %0, t; }" : "=r"(a) : "l"(p));
    return a;
}
__device__ __forceinline__ void ldm4(uint32_t* r, uint32_t addr) {
    asm volatile("ldmatrix.sync.aligned.m8n8.x4.shared.b16 {%0,%1,%2,%3}, [%4];"
        : "=r"(r[0]), "=r"(r[1]), "=r"(r[2]), "=r"(r[3]) : "r"(addr));
}
__device__ __forceinline__ void mma_bf16(float* d, const uint32_t* a, const uint32_t* b) {
    asm volatile(
        "mma.sync.aligned.m16n8k16.row.col.f32.bf16.bf16.f32 "
        "{%0,%1,%2,%3}, {%4,%5,%6,%7}, {%8,%9}, {%0,%1,%2,%3};"
        : "+f"(d[0]), "+f"(d[1]), "+f"(d[2]), "+f"(d[3])
        : "r"(a[0]), "r"(a[1]), "r"(a[2]), "r"(a[3]), "r"(b[0]), "r"(b[1]));
}
__device__ __forceinline__ void cp16(uint32_t saddr, const void* gaddr) {
    asm volatile("cp.async.cg.shared.global [%0], [%1], 16;" :: "r"(saddr), "l"(gaddr));
}
#define CP_COMMIT() asm volatile("cp.async.commit_group;" ::: "memory")
#define CP_WAIT0()  asm volatile("cp.async.wait_group 0;" ::: "memory")

__device__ __forceinline__ void split2(float x0, float x1, uint32_t& ph, uint32_t& pl) {
    __nv_bfloat16 h0 = __float2bfloat16(x0), h1 = __float2bfloat16(x1);
    float r0 = x0 - __bfloat162float(h0), r1 = x1 - __bfloat162float(h1);
    __nv_bfloat16 l0 = __float2bfloat16(r0), l1 = __float2bfloat16(r1);
    ph = ((uint32_t)__bfloat16_as_ushort(h1) << 16) | (uint32_t)__bfloat16_as_ushort(h0);
    pl = ((uint32_t)__bfloat16_as_ushort(l1) << 16) | (uint32_t)__bfloat16_as_ushort(l0);
}

// FMA-pipe exp for x <= 0 (magic-number exp2 + degree-5 poly)
__device__ __forceinline__ float fexp_neg(float x) {
    float z = fmaxf(x * 1.44269504f, -126.0f);
    float t = z + 12582912.0f;
    float n = t - 12582912.0f;
    float f = z - n;
    int   i = __float_as_int(t);
    float p = 1.3333558146e-3f;
    p = fmaf(p, f, 9.6181291076e-3f);
    p = fmaf(p, f, 5.5504108664e-2f);
    p = fmaf(p, f, 2.4022650696e-1f);
    p = fmaf(p, f, 6.9314718056e-1f);
    p = fmaf(p, f, 1.0f);
    float s = __int_as_float((((i & 0x7FFFFF) - 0x400000 + 127) << 23));
    return p * s;
}

// ---------------- graph prep ----------------
__global__ void k_zero_prep() {
    int i = blockIdx.x * 256 + threadIdx.x;
    if (i < NN) { g_degout[i] = 0; g_degin[i] = 0; g_fill[i] = 0; }
}
__global__ void k_count(const int* __restrict__ src, const int* __restrict__ dst) {
    int e = blockIdx.x * 256 + threadIdx.x;
    if (e < EE) { atomicAdd(&g_degout[src[e]], 1); atomicAdd(&g_degin[dst[e]], 1); }
}
__global__ void k_norms() {
    int i = blockIdx.x * 256 + threadIdx.x;
    if (i < NN) {
        g_ns[i] = rsqrtf((float)max(g_degout[i], 1));
        g_nd[i] = rsqrtf((float)max(g_degin[i], 1));
    }
}
__global__ void k_scan1() {
    __shared__ int s[1024];
    int tid = threadIdx.x;
    int i = blockIdx.x * 1024 + tid;
    int v = (i < NN) ? g_degin[i] : 0;
    s[tid] = v;
    __syncthreads();
    for (int off = 1; off < 1024; off <<= 1) {
        int t = (tid >= off) ? s[tid - off] : 0;
        __syncthreads(); s[tid] += t; __syncthreads();
    }
    g_incl[i] = s[tid];
    if (tid == 1023) g_bsum[blockIdx.x] = s[1023];
}
__global__ void k_scan2() {
    __shared__ int s[64];
    int tid = threadIdx.x;
    int v = (tid < 49) ? g_bsum[tid] : 0;
    s[tid] = v;
    __syncthreads();
    for (int off = 1; off < 64; off <<= 1) {
        int t = (tid >= off) ? s[tid - off] : 0;
        __syncthreads(); s[tid] += t; __syncthreads();
    }
    g_boff[tid] = s[tid] - v;
}
__global__ void k_scan3() {
    int i = blockIdx.x * 256 + threadIdx.x;
    if (i < NN) g_rowptr[i + 1] = g_incl[i] + g_boff[i >> 10];
    if (i == 0) g_rowptr[0] = 0;
}
__global__ void k_fill(const int* __restrict__ src, const int* __restrict__ dst) {
    int e = blockIdx.x * 256 + threadIdx.x;
    if (e < EE) {
        int d = dst[e];
        int pos = g_rowptr[d] + atomicAdd(&g_fill[d], 1);
        g_col[pos] = src[e];
    }
}

// ---------------- SpMM gather -> packed split-bf16 planes (norm_d fused) ----------------
__global__ void k_spmm(const float* __restrict__ X) {
    int node = blockIdx.x * 8 + threadIdx.y;
    if (node >= NN) return;
    int lane = threadIdx.x;
    float4 a0 = make_float4(0.f, 0.f, 0.f, 0.f);
    float4 a1 = make_float4(0.f, 0.f, 0.f, 0.f);
    int beg = g_rowptr[node], end = g_rowptr[node + 1];
    for (int e = beg; e < end; e++) {
        int s = g_col[e];
        float w = g_ns[s];
        const float4* row = (const float4*)(X + (size_t)s * DD);
        float4 v = row[lane];
        a0.x += w * v.x; a0.y += w * v.y; a0.z += w * v.z; a0.w += w * v.w;
        v = row[lane + 32];
        a1.x += w * v.x; a1.y += w * v.y; a1.z += w * v.z; a1.w += w * v.w;
    }
    float nd = g_nd[node];
    a0.x *= nd; a0.y *= nd; a0.z *= nd; a0.w *= nd;
    a1.x *= nd; a1.y *= nd; a1.z *= nd; a1.w *= nd;

    int kt = lane >> 3;
    size_t rb = (size_t)(node >> 7) * 8;
    uint32_t roff = (uint32_t)((node & 127) * AB_PITCH + (lane & 7) * 8);
    uint32_t h0, l0, h1, l1;

    split2(a0.x, a0.y, h0, l0);
    split2(a0.z, a0.w, h1, l1);
    size_t base = (rb + kt) * 10240 + roff;
    *(uint2*)(g_Ah + base) = make_uint2(h0, h1);
    *(uint2*)(g_Al + base) = make_uint2(l0, l1);

    split2(a1.x, a1.y, h0, l0);
    split2(a1.z, a1.w, h1, l1);
    base = (rb + 4 + kt) * 10240 + roff;
    *(uint2*)(g_Ah + base) = make_uint2(h0, h1);
    *(uint2*)(g_Al + base) = make_uint2(l0, l1);
}

// ---------------- weight prepack (bf16 split) ----------------
__global__ void k_prepack(const float* __restrict__ W, unsigned char* __restrict__ ph,
                          unsigned char* __restrict__ pl, int K) {
    int task = blockIdx.x * 256 + threadIdx.x;
    int nk8 = K >> 3;
    if (task >= DD * nk8) return;
    int n = task / nk8, k8 = task % nk8;
    int k0 = k8 << 3;
    float x[8];
    #pragma unroll
    for (int i = 0; i < 8; i++) x[i] = W[(size_t)(k0 + i) * DD + n];
    uint4 vh, vl;
    split2(x[0], x[1], vh.x, vl.x);
    split2(x[2], x[3], vh.y, vl.y);
    split2(x[4], x[5], vh.z, vl.z);
    split2(x[6], x[7], vh.w, vl.w);
    size_t off = (size_t)(k0 >> 5) * 20480 + (size_t)n * AB_PITCH + (k0 & 31) * 2;
    *(uint4*)(ph + off) = vh;
    *(uint4*)(pl + off) = vl;
}

// ================= 64x256 HMMA GEMM cores (bf16 3-product, 2 CTAs/SM) =================
// CTA 64x256, 256 thr, warps 2x4, warp tile 32x64
// smem buffer 51200: Ah@0(5120) Al@5120 Bh@10240(20480) Bl@30720(20480); x2 buffers
#define SM_AL_OFF 5120
#define SM_BH_OFF 10240
#define SM_BL_OFF 30720
#define BUF_SZ 51200
#define SMEM_GEMM 102400

// ---- fc: fp32 A split on the fly ----
__global__ void __launch_bounds__(256, 2) hmma_gemm_fc(
    const float* __restrict__ A,
    const unsigned char* __restrict__ Bh_g, const unsigned char* __restrict__ Bl_g,
    const float* __restrict__ bias, float* __restrict__ C, int M, int K)
{
    extern __shared__ __align__(16) unsigned char smem[];
    uint32_t sb = smem_to_u32(smem);
    int tid = threadIdx.x;
    int wid = tid >> 5, lane = tid & 31;
    int bm0 = blockIdx.x * 64;
    int nIter = K >> 5;

    // A tile 64 rows x 32 cols fp32: thread -> (row = tid/4, 8 cols)
    int arow = tid >> 2;
    int akq = (tid & 3) * 8;
    int agr = bm0 + arow;
    bool avalid = (agr < M);
    const float* aptr = A + (size_t)(avalid ? agr : 0) * K + akq;
    uint32_t a_soff = (uint32_t)(arow * AB_PITCH + akq * 2);

    int wr = wid >> 2, wc = wid & 3;     // 2 x 4 warps
    int mbase_w = wr * 32;
    int nbase_w = wc * 64;

    int lj = lane >> 3, lr = lane & 7;
    uint32_t aoffA = (uint32_t)(((lj & 1) * 8 + lr) * AB_PITCH + (lj >> 1) * 16);
    uint32_t aoffB = (uint32_t)(((lj >> 1) * 8 + lr) * AB_PITCH + (lj & 1) * 16);

    float acc[2][8][4];
    #pragma unroll
    for (int mt = 0; mt < 2; mt++)
        #pragma unroll
        for (int nt = 0; nt < 8; nt++)
            #pragma unroll
            for (int i = 0; i < 4; i++) acc[mt][nt][i] = 0.f;

    {
        for (int c = tid; c < 1280; c += 256) {
            cp16(sb + SM_BH_OFF + c * 16, Bh_g + c * 16);
            cp16(sb + SM_BL_OFF + c * 16, Bl_g + c * 16);
        }
        CP_COMMIT();
        float4 v0 = make_float4(0.f, 0.f, 0.f, 0.f), v1 = v0;
        if (avalid) { v0 = *(const float4*)(aptr); v1 = *(const float4*)(aptr + 4); }
        uint4 vh, vl;
        split2(v0.x, v0.y, vh.x, vl.x);
        split2(v0.z, v0.w, vh.y, vl.y);
        split2(v1.x, v1.y, vh.z, vl.z);
        split2(v1.z, v1.w, vh.w, vl.w);
        *(uint4*)(smem + a_soff) = vh;
        *(uint4*)(smem + SM_AL_OFF + a_soff) = vl;
        CP_WAIT0();
        __syncthreads();
    }

    for (int it = 0; it < nIter; it++) {
        uint32_t bufo = (uint32_t)((it & 1) * BUF_SZ);
        uint32_t nbufo = (uint32_t)(((it + 1) & 1) * BUF_SZ);
        bool more = (it + 1 < nIter);

        float4 v0 = make_float4(0.f, 0.f, 0.f, 0.f), v1 = v0;
        if (more) {
            size_t tb = (size_t)(it + 1) * 20480;
            for (int c = tid; c < 1280; c += 256) {
                cp16(sb + nbufo + SM_BH_OFF + c * 16, Bh_g + tb + c * 16);
                cp16(sb + nbufo + SM_BL_OFF + c * 16, Bl_g + tb + c * 16);
            }
            CP_COMMIT();
            if (avalid) {
                int k0 = (it + 1) << 5;
                v0 = *(const float4*)(aptr + k0);
                v1 = *(const float4*)(aptr + k0 + 4);
            }
        }

        #pragma unroll
        for (int ks = 0; ks < 2; ks++) {
            uint32_t kof = (uint32_t)(ks * 32);
            uint32_t ah[2][4], al[2][4];
            #pragma unroll
            for (int mt = 0; mt < 2; mt++) {
                uint32_t base = sb + bufo + (uint32_t)((mbase_w + mt * 16) * AB_PITCH) + kof + aoffA;
                ldm4(ah[mt], base);
                ldm4(al[mt], base + SM_AL_OFF);
            }
            #pragma unroll
            for (int np = 0; np < 4; np++) {
                uint32_t bbase = sb + bufo + SM_BH_OFF + (uint32_t)((nbase_w + np * 16) * AB_PITCH) + kof + aoffB;
                uint32_t rh[4], rl[4];
                ldm4(rh, bbase);
                ldm4(rl, bbase + 20480);
                #pragma unroll
                for (int mt = 0; mt < 2; mt++) {
                    mma_bf16(acc[mt][np * 2 + 0], ah[mt], rh + 0);
                    mma_bf16(acc[mt][np * 2 + 0], ah[mt], rl + 0);
                    mma_bf16(acc[mt][np * 2 + 0], al[mt], rh + 0);
                    mma_bf16(acc[mt][np * 2 + 1], ah[mt], rh + 2);
                    mma_bf16(acc[mt][np * 2 + 1], ah[mt], rl + 2);
                    mma_bf16(acc[mt][np * 2 + 1], al[mt], rh + 2);
                }
            }
        }

        if (more) {
            uint4 vh, vl;
            split2(v0.x, v0.y, vh.x, vl.x);
            split2(v0.z, v0.w, vh.y, vl.y);
            split2(v1.x, v1.y, vh.z, vl.z);
            split2(v1.z, v1.w, vh.w, vl.w);
            *(uint4*)(smem + nbufo + a_soff) = vh;
            *(uint4*)(smem + nbufo + SM_AL_OFF + a_soff) = vl;
            CP_WAIT0();
        }
        __syncthreads();
    }

    int g = lane >> 2, t2 = (lane & 3) * 2;
    #pragma unroll
    for (int mt = 0; mt < 2; mt++) {
        int r0 = bm0 + mbase_w + mt * 16 + g;
        int r1 = r0 + 8;
        #pragma unroll
        for (int nt = 0; nt < 8; nt++) {
            int c = nbase_w + nt * 8 + t2;
            float b0 = __ldg(&bias[c]), b1 = __ldg(&bias[c + 1]);
            if (r0 < M) *(float2*)(C + (size_t)r0 * DD + c) =
                make_float2(acc[mt][nt][0] + b0, acc[mt][nt][1] + b1);
            if (r1 < M) *(float2*)(C + (size_t)r1 * DD + c) =
                make_float2(acc[mt][nt][2] + b0, acc[mt][nt][3] + b1);
        }
    }
}

// ---- layer GEMM: packed split-bf16 A (64-row slice of 128-row packed blocks) ----
__global__ void __launch_bounds__(256, 2) hmma_gemm_pk(
    const unsigned char* __restrict__ Ah_g, const unsigned char* __restrict__ Al_g,
    const unsigned char* __restrict__ Bh_g, const unsigned char* __restrict__ Bl_g,
    const float* __restrict__ bias, float* __restrict__ C, int M)
{
    extern __shared__ __align__(16) unsigned char smem[];
    uint32_t sb = smem_to_u32(smem);
    int tid = threadIdx.x;
    int wid = tid >> 5, lane = tid & 31;
    int bm0 = blockIdx.x * 64;
    const int nIter = 8;
    // A slice: row-block = blockIdx.x>>1, half-offset = (blockIdx.x&1)*64 rows * 80B
    size_t abase = (size_t)(blockIdx.x >> 1) * 8 * 10240 + (size_t)(blockIdx.x & 1) * 5120;

    int wr = wid >> 2, wc = wid & 3;
    int mbase_w = wr * 32;
    int nbase_w = wc * 64;

    int lj = lane >> 3, lr = lane & 7;
    uint32_t aoffA = (uint32_t)(((lj & 1) * 8 + lr) * AB_PITCH + (lj >> 1) * 16);
    uint32_t aoffB = (uint32_t)(((lj >> 1) * 8 + lr) * AB_PITCH + (lj & 1) * 16);

    float acc[2][8][4];
    #pragma unroll
    for (int mt = 0; mt < 2; mt++)
        #pragma unroll
        for (int nt = 0; nt < 8; nt++)
            #pragma unroll
            for (int i = 0; i < 4; i++) acc[mt][nt][i] = 0.f;

    {
        for (int c = tid; c < 320; c += 256) {
            cp16(sb + c * 16, Ah_g + abase + c * 16);
            cp16(sb + SM_AL_OFF + c * 16, Al_g + abase + c * 16);
        }
        for (int c = tid; c < 1280; c += 256) {
            cp16(sb + SM_BH_OFF + c * 16, Bh_g + c * 16);
            cp16(sb + SM_BL_OFF + c * 16, Bl_g + c * 16);
        }
        CP_COMMIT();
        CP_WAIT0();
        __syncthreads();
    }

    for (int it = 0; it < nIter; it++) {
        uint32_t bufo = (uint32_t)((it & 1) * BUF_SZ);
        uint32_t nbufo = (uint32_t)(((it + 1) & 1) * BUF_SZ);
        bool more = (it + 1 < nIter);

        if (more) {
            size_t ta = abase + (size_t)(it + 1) * 10240;
            size_t tb = (size_t)(it + 1) * 20480;
            for (int c = tid; c < 320; c += 256) {
                cp16(sb + nbufo + c * 16, Ah_g + ta + c * 16);
                cp16(sb + nbufo + SM_AL_OFF + c * 16, Al_g + ta + c * 16);
            }
            for (int c = tid; c < 1280; c += 256) {
                cp16(sb + nbufo + SM_BH_OFF + c * 16, Bh_g + tb + c * 16);
                cp16(sb + nbufo + SM_BL_OFF + c * 16, Bl_g + tb + c * 16);
            }
            CP_COMMIT();
        }

        #pragma unroll
        for (int ks = 0; ks < 2; ks++) {
            uint32_t kof = (uint32_t)(ks * 32);
            uint32_t ah[2][4], al[2][4];
            #pragma unroll
            for (int mt = 0; mt < 2; mt++) {
                uint32_t base = sb + bufo + (uint32_t)((mbase_w + mt * 16) * AB_PITCH) + kof + aoffA;
                ldm4(ah[mt], base);
                ldm4(al[mt], base + SM_AL_OFF);
            }
            #pragma unroll
            for (int np = 0; np < 4; np++) {
                uint32_t bbase = sb + bufo + SM_BH_OFF + (uint32_t)((nbase_w + np * 16) * AB_PITCH) + kof + aoffB;
                uint32_t rh[4], rl[4];
                ldm4(rh, bbase);
                ldm4(rl, bbase + 20480);
                #pragma unroll
                for (int mt = 0; mt < 2; mt++) {
                    mma_bf16(acc[mt][np * 2 + 0], ah[mt], rh + 0);
                    mma_bf16(acc[mt][np * 2 + 0], ah[mt], rl + 0);
                    mma_bf16(acc[mt][np * 2 + 0], al[mt], rh + 0);
                    mma_bf16(acc[mt][np * 2 + 1], ah[mt], rh + 2);
                    mma_bf16(acc[mt][np * 2 + 1], ah[mt], rl + 2);
                    mma_bf16(acc[mt][np * 2 + 1], al[mt], rh + 2);
                }
            }
        }

        if (more) CP_WAIT0();
        __syncthreads();
    }

    int g = lane >> 2, t2 = (lane & 3) * 2;
    #pragma unroll
    for (int mt = 0; mt < 2; mt++) {
        int r0 = bm0 + mbase_w + mt * 16 + g;
        int r1 = r0 + 8;
        #pragma unroll
        for (int nt = 0; nt < 8; nt++) {
            int c = nbase_w + nt * 8 + t2;
            float b0 = __ldg(&bias[c]), b1 = __ldg(&bias[c + 1]);
            if (r0 < M) *(float2*)(C + (size_t)r0 * DD + c) =
                make_float2(acc[mt][nt][0] + b0, acc[mt][nt][1] + b1);
            if (r1 < M) *(float2*)(C + (size_t)r1 * DD + c) =
                make_float2(acc[mt][nt][2] + b0, acc[mt][nt][3] + b1);
        }
    }
}

// ---------------- BatchNorm + ELU ----------------
__global__ void k_zero_bn() {
    int c = threadIdx.x;
    g_bns[c] = 0.f;
    g_bnq[c] = 0.f;
}
__global__ void k_bn_stats(const float* __restrict__ X) {
    int c = threadIdx.x;
    int r0 = blockIdx.x * 256;
    int r1 = min(r0 + 256, NN);
    float s = 0.f, q = 0.f;
    for (int r = r0; r < r1; r++) {
        float v = X[(size_t)r * DD + c];
        s += v; q += v * v;
    }
    atomicAdd(&g_bns[c], s);
    atomicAdd(&g_bnq[c], q);
}
__global__ void k_bn_apply(float* __restrict__ X,
                           const float* __restrict__ gamma,
                           const float* __restrict__ beta) {
    int idx = blockIdx.x * 256 + threadIdx.x;
    if (idx >= NN * (DD / 4)) return;
    int c4 = idx & 63;
    int c = c4 * 4;
    const float invN = 1.f / (float)NN;
    float4 sm = *(const float4*)&g_bns[c];
    float4 sq = *(const float4*)&g_bnq[c];
    float4 gm = *(const float4*)&gamma[c];
    float4 bt = *(const float4*)&beta[c];
    float mu, var, sc;
    float4 x = ((float4*)X)[idx];
    float4 y;
    mu = sm.x * invN; var = sq.x * invN - mu * mu; sc = gm.x * rsqrtf(var + 1e-5f);
    y.x = sc * (x.x - mu) + bt.x;
    mu = sm.y * invN; var = sq.y * invN - mu * mu; sc = gm.y * rsqrtf(var + 1e-5f);
    y.y = sc * (x.y - mu) + bt.y;
    mu = sm.z * invN; var = sq.z * invN - mu * mu; sc = gm.z * rsqrtf(var + 1e-5f);
    y.z = sc * (x.z - mu) + bt.z;
    mu = sm.w * invN; var = sq.w * invN - mu * mu; sc = gm.w * rsqrtf(var + 1e-5f);
    y.w = sc * (x.w - mu) + bt.w;
    y.x = (y.x > 0.f) ? y.x : (__expf(y.x) - 1.f);
    y.y = (y.y > 0.f) ? y.y : (fexp_neg(y.y) - 1.f);
    y.z = (y.z > 0.f) ? y.z : (__expf(y.z) - 1.f);
    y.w = (y.w > 0.f) ? y.w : (fexp_neg(y.w) - 1.f);
    ((float4*)X)[idx] = y;
}

// ---------------- logits GEMM ----------------
__global__ __launch_bounds__(320) void k_logits(
    const float* __restrict__ X, const float* __restrict__ W,
    const float* __restrict__ bias, float* __restrict__ O, int M)
{
    __shared__ float Xs[32][68];
    __shared__ float Ws[32][40];
    int tid = threadIdx.x;
    int bm0 = blockIdx.x * 64;
    int rg = tid / 40;
    int col = tid % 40;
    float acc[8];
    #pragma unroll
    for (int i = 0; i < 8; i++) acc[i] = 0.f;

    for (int k0 = 0; k0 < DD; k0 += 32) {
        for (int idx = tid; idx < 512; idx += 320) {
            int row = idx >> 3;
            int kq = idx & 7;
            float4 v = make_float4(0.f, 0.f, 0.f, 0.f);
            int gr = bm0 + row;
            if (gr < M) v = *(const float4*)(X + (size_t)gr * DD + k0 + kq * 4);
            Xs[kq * 4 + 0][row] = v.x;
            Xs[kq * 4 + 1][row] = v.y;
            Xs[kq * 4 + 2][row] = v.z;
            Xs[kq * 4 + 3][row] = v.w;
        }
        for (int idx = tid; idx < 1280; idx += 320) {
            int k = idx / 40, c = idx % 40;
            Ws[k][c] = W[(size_t)(k0 + k) * CC + c];
        }
        __syncthreads();
        #pragma unroll
        for (int kk = 0; kk < 32; kk++) {
            float w = Ws[kk][col];
            float a0[4], a1[4];
            *(float4*)&a0[0] = *(float4*)&Xs[kk][rg * 8];
            *(float4*)&a1[0] = *(float4*)&Xs[kk][rg * 8 + 4];
            acc[0] += a0[0] * w; acc[1] += a0[1] * w;
            acc[2] += a0[2] * w; acc[3] += a0[3] * w;
            acc[4] += a1[0] * w; acc[5] += a1[1] * w;
            acc[6] += a1[2] * w; acc[7] += a1[3] * w;
        }
        __syncthreads();
    }
    float b = bias[col];
    #pragma unroll
    for (int i = 0; i < 8; i++) {
        int r = bm0 + rg * 8 + i;
        if (r < M) O[(size_t)r * CC + col] = acc[i] + b;
    }
}

// ---------------- static stream/event init ----------------
struct SideRes {
    cudaStream_t sB;
    cudaEvent_t evFork, evJoin;
    SideRes() {
        cudaStreamCreateWithFlags(&sB, cudaStreamNonBlocking);
        cudaEventCreateWithFlags(&evFork, cudaEventDisableTiming);
        cudaEventCreateWithFlags(&evJoin, cudaEventDisableTiming);
        cudaFuncSetAttribute(hmma_gemm_fc, cudaFuncAttributeMaxDynamicSharedMemorySize, SMEM_GEMM);
        cudaFuncSetAttribute(hmma_gemm_pk, cudaFuncAttributeMaxDynamicSharedMemorySize, SMEM_GEMM);
    }
};
static SideRes g_sr;

// ---------------- driver ----------------
extern "C" void kernel_launch(void* const* d_in, const int* in_sizes, int n_in,
                              void* d_out, int out_size)
{
    const float* feat  = (const float*)d_in[0];
    const int*   src   = (const int*)d_in[1];
    const int*   dst   = (const int*)d_in[2];
    const float* W_fc  = (const float*)d_in[3];
    const float* b_fc  = (const float*)d_in[4];
    const float* W1    = (const float*)d_in[5];
    const float* b1    = (const float*)d_in[6];
    const float* W2    = (const float*)d_in[7];
    const float* b2    = (const float*)d_in[8];
    const float* W3    = (const float*)d_in[9];
    const float* b3    = (const float*)d_in[10];
    const float* gamma = (const float*)d_in[11];
    const float* beta  = (const float*)d_in[12];
    const float* W_lin = (const float*)d_in[13];
    const float* b_lin = (const float*)d_in[14];
    float* out = (float*)d_out;

    float* gX;  cudaGetSymbolAddress((void**)&gX, g_X);
    unsigned char *gAh, *gAl;
    cudaGetSymbolAddress((void**)&gAh, g_Ah);
    cudaGetSymbolAddress((void**)&gAl, g_Al);
    unsigned char *pFh, *pFl, *p1h, *p1l, *p2h, *p2l, *p3h, *p3l;
    cudaGetSymbolAddress((void**)&pFh, g_Wfc_h);
    cudaGetSymbolAddress((void**)&pFl, g_Wfc_l);
    cudaGetSymbolAddress((void**)&p1h, g_W1_h);
    cudaGetSymbolAddress((void**)&p1l, g_W1_l);
    cudaGetSymbolAddress((void**)&p2h, g_W2_h);
    cudaGetSymbolAddress((void**)&p2l, g_W2_l);
    cudaGetSymbolAddress((void**)&p3h, g_W3_h);
    cudaGetSymbolAddress((void**)&p3l, g_W3_l);

    const int NB_N = (NN + 255) / 256;
    const int NB_E = (EE + 255) / 256;
    const int GEMM_GRID = (NN + 63) / 64;   // 782 (64-row CTAs)
    dim3 spmm_block(32, 8);
    int spmm_grid = (NN + 7) / 8;
    int bn_grid = (NN * (DD / 4) + 255) / 256;

    // fork
    cudaEventRecord(g_sr.evFork, 0);
    cudaStreamWaitEvent(g_sr.sB, g_sr.evFork, 0);

    k_zero_prep<<<NB_N, 256, 0, g_sr.sB>>>();
    k_count<<<NB_E, 256, 0, g_sr.sB>>>(src, dst);
    k_prepack<<<(DD * (FF / 8) + 255) / 256, 256>>>(W_fc, pFh, pFl, FF);            // main
    hmma_gemm_fc<<<GEMM_GRID, 256, SMEM_GEMM>>>(feat, pFh, pFl, b_fc, gX, NN, FF);  // main
    k_norms<<<NB_N, 256, 0, g_sr.sB>>>();
    k_scan1<<<49, 1024, 0, g_sr.sB>>>();
    k_scan2<<<1, 64, 0, g_sr.sB>>>();
    k_scan3<<<NB_N, 256, 0, g_sr.sB>>>();
    k_fill<<<NB_E, 256, 0, g_sr.sB>>>(src, dst);
    k_prepack<<<(DD * (DD / 8) + 255) / 256, 256, 0, g_sr.sB>>>(W1, p1h, p1l, DD);
    k_prepack<<<(DD * (DD / 8) + 255) / 256, 256, 0, g_sr.sB>>>(W2, p2h, p2l, DD);
    k_prepack<<<(DD * (DD / 8) + 255) / 256, 256, 0, g_sr.sB>>>(W3, p3h, p3l, DD);
    k_zero_bn<<<1, 256, 0, g_sr.sB>>>();
    cudaEventRecord(g_sr.evJoin, g_sr.sB);

    // join
    cudaStreamWaitEvent(0, g_sr.evJoin, 0);

    // layer 1
    k_spmm<<<spmm_grid, spmm_block>>>(gX);
    hmma_gemm_pk<<<GEMM_GRID, 256, SMEM_GEMM>>>(gAh, gAl, p1h, p1l, b1, gX, NN);
    k_bn_stats<<<NB_N, 256>>>(gX);
    k_bn_apply<<<bn_grid, 256>>>(gX, gamma, beta);
    k_zero_bn<<<1, 256>>>();

    // layer 2
    k_spmm<<<spmm_grid, spmm_block>>>(gX);
    hmma_gemm_pk<<<GEMM_GRID, 256, SMEM_GEMM>>>(gAh, gAl, p2h, p2l, b2, gX, NN);
    k_bn_stats<<<NB_N, 256>>>(gX);
    k_bn_apply<<<bn_grid, 256>>>(gX, gamma, beta);

    // layer 3 -> features into d_out[0 : N*D)
    k_spmm<<<spmm_grid, spmm_block>>>(gX);
    hmma_gemm_pk<<<GEMM_GRID, 256, SMEM_GEMM>>>(gAh, gAl, p3h, p3l, b3, out, NN);

    // logits -> d_out[N*D : )
    k_logits<<<(NN + 63) / 64, 320>>>(out, W_lin, b_lin, out + (size_t)NN * DD, NN);
}

// round 12
// speedup vs baseline: 1.4535x; 1.0763x over previous
#include <cuda_runtime.h>
#include <cuda_bf16.h>
#include <cuda_fp16.h>
#include <math.h>
#include <stdint.h>

#define NN 50000
#define EE 300000
#define DD 256
#define FF 1024
#define CC 40
#define AB_PITCH 80

// ---------------- scratch (static device globals; no allocation) ----------------
__device__ __half g_X16[NN * DD];       // inter-layer activations, fp16
__device__ float g_ns[NN];
__device__ float g_nd[NN];
__device__ int   g_degout[NN];
__device__ int   g_degin[NN];
__device__ int   g_fill[NN];
__device__ int   g_incl[49 * 1024];
__device__ int   g_bsum[64];
__device__ int   g_boff[64];
__device__ int   g_rowptr[NN + 1];
__device__ int   g_col[EE];
__device__ float g_bns[DD];
__device__ float g_bnq[DD];

// packed split-bf16 A planes written by spmm: per (rowblk, ktile): 128 rows x 80B
__device__ __align__(16) unsigned char g_Ah[391 * 8 * 10240];
__device__ __align__(16) unsigned char g_Al[391 * 8 * 10240];

// prepacked weights: per ktile: 256 n-rows x 80B = 20480 B (bf16 hi/lo planes)
__device__ __align__(16) unsigned char g_Wfc_h[32 * 20480];
__device__ __align__(16) unsigned char g_Wfc_l[32 * 20480];
__device__ __align__(16) unsigned char g_W1_h[8 * 20480];
__device__ __align__(16) unsigned char g_W1_l[8 * 20480];
__device__ __align__(16) unsigned char g_W2_h[8 * 20480];
__device__ __align__(16) unsigned char g_W2_l[8 * 20480];
__device__ __align__(16) unsigned char g_W3_h[8 * 20480];
__device__ __align__(16) unsigned char g_W3_l[8 * 20480];

// ================= helpers =================
__device__ __forceinline__ uint32_t smem_to_u32(const void* p) {
    uint32_t a;
    asm("{ .reg .u64 t; cvta.to.shared.u64 t, %1; cvt.u32.u64 %0, t; }" : "=r"(a) : "l"(p));
    return a;
}
__device__ __forceinline__ void ldm4(uint32_t* r, uint32_t addr) {
    asm volatile("ldmatrix.sync.aligned.m8n8.x4.shared.b16 {%0,%1,%2,%3}, [%4];"
        : "=r"(r[0]), "=r"(r[1]), "=r"(r[2]), "=r"(r[3]) : "r"(addr));
}
__device__ __forceinline__ void mma_bf16(float* d, const uint32_t* a, const uint32_t* b) {
    asm volatile(
        "mma.sync.aligned.m16n8k16.row.col.f32.bf16.bf16.f32 "
        "{%0,%1,%2,%3}, {%4,%5,%6,%7}, {%8,%9}, {%0,%1,%2,%3};"
        : "+f"(d[0]), "+f"(d[1]), "+f"(d[2]), "+f"(d[3])
        : "r"(a[0]), "r"(a[1]), "r"(a[2]), "r"(a[3]), "r"(b[0]), "r"(b[1]));
}
__device__ __forceinline__ void cp16(uint32_t saddr, const void* gaddr) {
    asm volatile("cp.async.cg.shared.global [%0], [%1], 16;" :: "r"(saddr), "l"(gaddr));
}
#define CP_COMMIT() asm volatile("cp.async.commit_group;" ::: "memory")
#define CP_WAIT0()  asm volatile("cp.async.wait_group 0;" ::: "memory")

__device__ __forceinline__ void split2(float x0, float x1, uint32_t& ph, uint32_t& pl) {
    __nv_bfloat16 h0 = __float2bfloat16(x0), h1 = __float2bfloat16(x1);
    float r0 = x0 - __bfloat162float(h0), r1 = x1 - __bfloat162float(h1);
    __nv_bfloat16 l0 = __float2bfloat16(r0), l1 = __float2bfloat16(r1);
    ph = ((uint32_t)__bfloat16_as_ushort(h1) << 16) | (uint32_t)__bfloat16_as_ushort(h0);
    pl = ((uint32_t)__bfloat16_as_ushort(l1) << 16) | (uint32_t)__bfloat16_as_ushort(l0);
}

// FMA-pipe exp for x <= 0 (magic-number exp2 + degree-5 poly)
__device__ __forceinline__ float fexp_neg(float x) {
    float z = fmaxf(x * 1.44269504f, -126.0f);
    float t = z + 12582912.0f;
    float n = t - 12582912.0f;
    float f = z - n;
    int   i = __float_as_int(t);
    float p = 1.3333558146e-3f;
    p = fmaf(p, f, 9.6181291076e-3f);
    p = fmaf(p, f, 5.5504108664e-2f);
    p = fmaf(p, f, 2.4022650696e-1f);
    p = fmaf(p, f, 6.9314718056e-1f);
    p = fmaf(p, f, 1.0f);
    float s = __int_as_float((((i & 0x7FFFFF) - 0x400000 + 127) << 23));
    return p * s;
}

// ---------------- graph prep ----------------
__global__ void k_zero_prep() {
    int i = blockIdx.x * 256 + threadIdx.x;
    if (i < NN) { g_degout[i] = 0; g_degin[i] = 0; g_fill[i] = 0; }
}
__global__ void k_count(const int* __restrict__ src, const int* __restrict__ dst) {
    int e = blockIdx.x * 256 + threadIdx.x;
    if (e < EE) { atomicAdd(&g_degout[src[e]], 1); atomicAdd(&g_degin[dst[e]], 1); }
}
__global__ void k_norms() {
    int i = blockIdx.x * 256 + threadIdx.x;
    if (i < NN) {
        g_ns[i] = rsqrtf((float)max(g_degout[i], 1));
        g_nd[i] = rsqrtf((float)max(g_degin[i], 1));
    }
}
__global__ void k_scan1() {
    __shared__ int s[1024];
    int tid = threadIdx.x;
    int i = blockIdx.x * 1024 + tid;
    int v = (i < NN) ? g_degin[i] : 0;
    s[tid] = v;
    __syncthreads();
    for (int off = 1; off < 1024; off <<= 1) {
        int t = (tid >= off) ? s[tid - off] : 0;
        __syncthreads(); s[tid] += t; __syncthreads();
    }
    g_incl[i] = s[tid];
    if (tid == 1023) g_bsum[blockIdx.x] = s[1023];
}
__global__ void k_scan2() {
    __shared__ int s[64];
    int tid = threadIdx.x;
    int v = (tid < 49) ? g_bsum[tid] : 0;
    s[tid] = v;
    __syncthreads();
    for (int off = 1; off < 64; off <<= 1) {
        int t = (tid >= off) ? s[tid - off] : 0;
        __syncthreads(); s[tid] += t; __syncthreads();
    }
    g_boff[tid] = s[tid] - v;
}
__global__ void k_scan3() {
    int i = blockIdx.x * 256 + threadIdx.x;
    if (i < NN) g_rowptr[i + 1] = g_incl[i] + g_boff[i >> 10];
    if (i == 0) g_rowptr[0] = 0;
}
__global__ void k_fill(const int* __restrict__ src, const int* __restrict__ dst) {
    int e = blockIdx.x * 256 + threadIdx.x;
    if (e < EE) {
        int d = dst[e];
        int pos = g_rowptr[d] + atomicAdd(&g_fill[d], 1);
        g_col[pos] = src[e];
    }
}

// ---------------- SpMM gather (fp16 X) -> packed split-bf16 planes (norm_d fused) ----------------
// lane L handles feature elems 8L..8L+7 (one uint4 = 8 halfs per edge)
__global__ void k_spmm(const __half* __restrict__ X) {
    int node = blockIdx.x * 8 + threadIdx.y;
    if (node >= NN) return;
    int lane = threadIdx.x;
    float acc[8];
    #pragma unroll
    for (int i = 0; i < 8; i++) acc[i] = 0.f;

    int beg = g_rowptr[node], end = g_rowptr[node + 1];
    int e = beg;
    for (; e + 1 < end; e += 2) {
        int s0 = g_col[e], s1 = g_col[e + 1];
        float w0 = g_ns[s0], w1 = g_ns[s1];
        uint4 u0 = *(const uint4*)(X + (size_t)s0 * DD + lane * 8);
        uint4 u1 = *(const uint4*)(X + (size_t)s1 * DD + lane * 8);
        const __half2* h0 = (const __half2*)&u0;
        const __half2* h1 = (const __half2*)&u1;
        #pragma unroll
        for (int q = 0; q < 4; q++) {
            float2 f0 = __half22float2(h0[q]);
            float2 f1 = __half22float2(h1[q]);
            acc[q * 2 + 0] += w0 * f0.x + w1 * f1.x;
            acc[q * 2 + 1] += w0 * f0.y + w1 * f1.y;
        }
    }
    if (e < end) {
        int s0 = g_col[e];
        float w0 = g_ns[s0];
        uint4 u0 = *(const uint4*)(X + (size_t)s0 * DD + lane * 8);
        const __half2* h0 = (const __half2*)&u0;
        #pragma unroll
        for (int q = 0; q < 4; q++) {
            float2 f0 = __half22float2(h0[q]);
            acc[q * 2 + 0] += w0 * f0.x;
            acc[q * 2 + 1] += w0 * f0.y;
        }
    }
    float nd = g_nd[node];
    #pragma unroll
    for (int i = 0; i < 8; i++) acc[i] *= nd;

    // packed layout: lane L -> ktile = L/4, inner byte = (L%4)*16
    uint4 vh, vl;
    split2(acc[0], acc[1], vh.x, vl.x);
    split2(acc[2], acc[3], vh.y, vl.y);
    split2(acc[4], acc[5], vh.z, vl.z);
    split2(acc[6], acc[7], vh.w, vl.w);
    size_t base = ((size_t)(node >> 7) * 8 + (lane >> 2)) * 10240
                + (uint32_t)((node & 127) * AB_PITCH + (lane & 3) * 16);
    *(uint4*)(g_Ah + base) = vh;
    *(uint4*)(g_Al + base) = vl;
}

// ---------------- weight prepack (bf16 split) ----------------
__global__ void k_prepack(const float* __restrict__ W, unsigned char* __restrict__ ph,
                          unsigned char* __restrict__ pl, int K) {
    int task = blockIdx.x * 256 + threadIdx.x;
    int nk8 = K >> 3;
    if (task >= DD * nk8) return;
    int n = task / nk8, k8 = task % nk8;
    int k0 = k8 << 3;
    float x[8];
    #pragma unroll
    for (int i = 0; i < 8; i++) x[i] = W[(size_t)(k0 + i) * DD + n];
    uint4 vh, vl;
    split2(x[0], x[1], vh.x, vl.x);
    split2(x[2], x[3], vh.y, vl.y);
    split2(x[4], x[5], vh.z, vl.z);
    split2(x[6], x[7], vh.w, vl.w);
    size_t off = (size_t)(k0 >> 5) * 20480 + (size_t)n * AB_PITCH + (k0 & 31) * 2;
    *(uint4*)(ph + off) = vh;
    *(uint4*)(pl + off) = vl;
}

// ================= 64x256 HMMA GEMM cores (bf16 3-product, 2 CTAs/SM) =================
#define SM_AL_OFF 5120
#define SM_BH_OFF 10240
#define SM_BL_OFF 30720
#define BUF_SZ 51200
#define SMEM_GEMM 102400

// ---- fc: fp32 A split on the fly; writes fp16 X ----
__global__ void __launch_bounds__(256, 2) hmma_gemm_fc(
    const float* __restrict__ A,
    const unsigned char* __restrict__ Bh_g, const unsigned char* __restrict__ Bl_g,
    const float* __restrict__ bias, __half* __restrict__ C, int M, int K)
{
    extern __shared__ __align__(16) unsigned char smem[];
    uint32_t sb = smem_to_u32(smem);
    int tid = threadIdx.x;
    int wid = tid >> 5, lane = tid & 31;
    int bm0 = blockIdx.x * 64;
    int nIter = K >> 5;

    int arow = tid >> 2;
    int akq = (tid & 3) * 8;
    int agr = bm0 + arow;
    bool avalid = (agr < M);
    const float* aptr = A + (size_t)(avalid ? agr : 0) * K + akq;
    uint32_t a_soff = (uint32_t)(arow * AB_PITCH + akq * 2);

    int wr = wid >> 2, wc = wid & 3;
    int mbase_w = wr * 32;
    int nbase_w = wc * 64;

    int lj = lane >> 3, lr = lane & 7;
    uint32_t aoffA = (uint32_t)(((lj & 1) * 8 + lr) * AB_PITCH + (lj >> 1) * 16);
    uint32_t aoffB = (uint32_t)(((lj >> 1) * 8 + lr) * AB_PITCH + (lj & 1) * 16);

    float acc[2][8][4];
    #pragma unroll
    for (int mt = 0; mt < 2; mt++)
        #pragma unroll
        for (int nt = 0; nt < 8; nt++)
            #pragma unroll
            for (int i = 0; i < 4; i++) acc[mt][nt][i] = 0.f;

    {
        for (int c = tid; c < 1280; c += 256) {
            cp16(sb + SM_BH_OFF + c * 16, Bh_g + c * 16);
            cp16(sb + SM_BL_OFF + c * 16, Bl_g + c * 16);
        }
        CP_COMMIT();
        float4 v0 = make_float4(0.f, 0.f, 0.f, 0.f), v1 = v0;
        if (avalid) { v0 = *(const float4*)(aptr); v1 = *(const float4*)(aptr + 4); }
        uint4 vh, vl;
        split2(v0.x, v0.y, vh.x, vl.x);
        split2(v0.z, v0.w, vh.y, vl.y);
        split2(v1.x, v1.y, vh.z, vl.z);
        split2(v1.z, v1.w, vh.w, vl.w);
        *(uint4*)(smem + a_soff) = vh;
        *(uint4*)(smem + SM_AL_OFF + a_soff) = vl;
        CP_WAIT0();
        __syncthreads();
    }

    for (int it = 0; it < nIter; it++) {
        uint32_t bufo = (uint32_t)((it & 1) * BUF_SZ);
        uint32_t nbufo = (uint32_t)(((it + 1) & 1) * BUF_SZ);
        bool more = (it + 1 < nIter);

        float4 v0 = make_float4(0.f, 0.f, 0.f, 0.f), v1 = v0;
        if (more) {
            size_t tb = (size_t)(it + 1) * 20480;
            for (int c = tid; c < 1280; c += 256) {
                cp16(sb + nbufo + SM_BH_OFF + c * 16, Bh_g + tb + c * 16);
                cp16(sb + nbufo + SM_BL_OFF + c * 16, Bl_g + tb + c * 16);
            }
            CP_COMMIT();
            if (avalid) {
                int k0 = (it + 1) << 5;
                v0 = *(const float4*)(aptr + k0);
                v1 = *(const float4*)(aptr + k0 + 4);
            }
        }

        #pragma unroll
        for (int ks = 0; ks < 2; ks++) {
            uint32_t kof = (uint32_t)(ks * 32);
            uint32_t ah[2][4], al[2][4];
            #pragma unroll
            for (int mt = 0; mt < 2; mt++) {
                uint32_t base = sb + bufo + (uint32_t)((mbase_w + mt * 16) * AB_PITCH) + kof + aoffA;
                ldm4(ah[mt], base);
                ldm4(al[mt], base + SM_AL_OFF);
            }
            #pragma unroll
            for (int np = 0; np < 4; np++) {
                uint32_t bbase = sb + bufo + SM_BH_OFF + (uint32_t)((nbase_w + np * 16) * AB_PITCH) + kof + aoffB;
                uint32_t rh[4], rl[4];
                ldm4(rh, bbase);
                ldm4(rl, bbase + 20480);
                #pragma unroll
                for (int mt = 0; mt < 2; mt++) {
                    mma_bf16(acc[mt][np * 2 + 0], ah[mt], rh + 0);
                    mma_bf16(acc[mt][np * 2 + 0], ah[mt], rl + 0);
                    mma_bf16(acc[mt][np * 2 + 0], al[mt], rh + 0);
                    mma_bf16(acc[mt][np * 2 + 1], ah[mt], rh + 2);
                    mma_bf16(acc[mt][np * 2 + 1], ah[mt], rl + 2);
                    mma_bf16(acc[mt][np * 2 + 1], al[mt], rh + 2);
                }
            }
        }

        if (more) {
            uint4 vh, vl;
            split2(v0.x, v0.y, vh.x, vl.x);
            split2(v0.z, v0.w, vh.y, vl.y);
            split2(v1.x, v1.y, vh.z, vl.z);
            split2(v1.z, v1.w, vh.w, vl.w);
            *(uint4*)(smem + nbufo + a_soff) = vh;
            *(uint4*)(smem + nbufo + SM_AL_OFF + a_soff) = vl;
            CP_WAIT0();
        }
        __syncthreads();
    }

    int g = lane >> 2, t2 = (lane & 3) * 2;
    #pragma unroll
    for (int mt = 0; mt < 2; mt++) {
        int r0 = bm0 + mbase_w + mt * 16 + g;
        int r1 = r0 + 8;
        #pragma unroll
        for (int nt = 0; nt < 8; nt++) {
            int c = nbase_w + nt * 8 + t2;
            float b0 = __ldg(&bias[c]), b1 = __ldg(&bias[c + 1]);
            if (r0 < M) *(__half2*)(C + (size_t)r0 * DD + c) =
                __floats2half2_rn(acc[mt][nt][0] + b0, acc[mt][nt][1] + b1);
            if (r1 < M) *(__half2*)(C + (size_t)r1 * DD + c) =
                __floats2half2_rn(acc[mt][nt][2] + b0, acc[mt][nt][3] + b1);
        }
    }
}

// ---- layer GEMM: packed split-bf16 A; output fp16 (layers 1,2) or fp32 (layer 3) ----
template <bool HALF_OUT>
__global__ void __launch_bounds__(256, 2) hmma_gemm_pk(
    const unsigned char* __restrict__ Ah_g, const unsigned char* __restrict__ Al_g,
    const unsigned char* __restrict__ Bh_g, const unsigned char* __restrict__ Bl_g,
    const float* __restrict__ bias, void* __restrict__ Cv, int M)
{
    extern __shared__ __align__(16) unsigned char smem[];
    uint32_t sb = smem_to_u32(smem);
    int tid = threadIdx.x;
    int wid = tid >> 5, lane = tid & 31;
    int bm0 = blockIdx.x * 64;
    const int nIter = 8;
    size_t abase = (size_t)(blockIdx.x >> 1) * 8 * 10240 + (size_t)(blockIdx.x & 1) * 5120;

    int wr = wid >> 2, wc = wid & 3;
    int mbase_w = wr * 32;
    int nbase_w = wc * 64;

    int lj = lane >> 3, lr = lane & 7;
    uint32_t aoffA = (uint32_t)(((lj & 1) * 8 + lr) * AB_PITCH + (lj >> 1) * 16);
    uint32_t aoffB = (uint32_t)(((lj >> 1) * 8 + lr) * AB_PITCH + (lj & 1) * 16);

    float acc[2][8][4];
    #pragma unroll
    for (int mt = 0; mt < 2; mt++)
        #pragma unroll
        for (int nt = 0; nt < 8; nt++)
            #pragma unroll
            for (int i = 0; i < 4; i++) acc[mt][nt][i] = 0.f;

    {
        for (int c = tid; c < 320; c += 256) {
            cp16(sb + c * 16, Ah_g + abase + c * 16);
            cp16(sb + SM_AL_OFF + c * 16, Al_g + abase + c * 16);
        }
        for (int c = tid; c < 1280; c += 256) {
            cp16(sb + SM_BH_OFF + c * 16, Bh_g + c * 16);
            cp16(sb + SM_BL_OFF + c * 16, Bl_g + c * 16);
        }
        CP_COMMIT();
        CP_WAIT0();
        __syncthreads();
    }

    for (int it = 0; it < nIter; it++) {
        uint32_t bufo = (uint32_t)((it & 1) * BUF_SZ);
        uint32_t nbufo = (uint32_t)(((it + 1) & 1) * BUF_SZ);
        bool more = (it + 1 < nIter);

        if (more) {
            size_t ta = abase + (size_t)(it + 1) * 10240;
            size_t tb = (size_t)(it + 1) * 20480;
            for (int c = tid; c < 320; c += 256) {
                cp16(sb + nbufo + c * 16, Ah_g + ta + c * 16);
                cp16(sb + nbufo + SM_AL_OFF + c * 16, Al_g + ta + c * 16);
            }
            for (int c = tid; c < 1280; c += 256) {
                cp16(sb + nbufo + SM_BH_OFF + c * 16, Bh_g + tb + c * 16);
                cp16(sb + nbufo + SM_BL_OFF + c * 16, Bl_g + tb + c * 16);
            }
            CP_COMMIT();
        }

        #pragma unroll
        for (int ks = 0; ks < 2; ks++) {
            uint32_t kof = (uint32_t)(ks * 32);
            uint32_t ah[2][4], al[2][4];
            #pragma unroll
            for (int mt = 0; mt < 2; mt++) {
                uint32_t base = sb + bufo + (uint32_t)((mbase_w + mt * 16) * AB_PITCH) + kof + aoffA;
                ldm4(ah[mt], base);
                ldm4(al[mt], base + SM_AL_OFF);
            }
            #pragma unroll
            for (int np = 0; np < 4; np++) {
                uint32_t bbase = sb + bufo + SM_BH_OFF + (uint32_t)((nbase_w + np * 16) * AB_PITCH) + kof + aoffB;
                uint32_t rh[4], rl[4];
                ldm4(rh, bbase);
                ldm4(rl, bbase + 20480);
                #pragma unroll
                for (int mt = 0; mt < 2; mt++) {
                    mma_bf16(acc[mt][np * 2 + 0], ah[mt], rh + 0);
                    mma_bf16(acc[mt][np * 2 + 0], ah[mt], rl + 0);
                    mma_bf16(acc[mt][np * 2 + 0], al[mt], rh + 0);
                    mma_bf16(acc[mt][np * 2 + 1], ah[mt], rh + 2);
                    mma_bf16(acc[mt][np * 2 + 1], ah[mt], rl + 2);
                    mma_bf16(acc[mt][np * 2 + 1], al[mt], rh + 2);
                }
            }
        }

        if (more) CP_WAIT0();
        __syncthreads();
    }

    int g = lane >> 2, t2 = (lane & 3) * 2;
    #pragma unroll
    for (int mt = 0; mt < 2; mt++) {
        int r0 = bm0 + mbase_w + mt * 16 + g;
        int r1 = r0 + 8;
        #pragma unroll
        for (int nt = 0; nt < 8; nt++) {
            int c = nbase_w + nt * 8 + t2;
            float b0 = __ldg(&bias[c]), b1 = __ldg(&bias[c + 1]);
            if (HALF_OUT) {
                __half* C = (__half*)Cv;
                if (r0 < M) *(__half2*)(C + (size_t)r0 * DD + c) =
                    __floats2half2_rn(acc[mt][nt][0] + b0, acc[mt][nt][1] + b1);
                if (r1 < M) *(__half2*)(C + (size_t)r1 * DD + c) =
                    __floats2half2_rn(acc[mt][nt][2] + b0, acc[mt][nt][3] + b1);
            } else {
                float* C = (float*)Cv;
                if (r0 < M) *(float2*)(C + (size_t)r0 * DD + c) =
                    make_float2(acc[mt][nt][0] + b0, acc[mt][nt][1] + b1);
                if (r1 < M) *(float2*)(C + (size_t)r1 * DD + c) =
                    make_float2(acc[mt][nt][2] + b0, acc[mt][nt][3] + b1);
            }
        }
    }
}

// ---------------- BatchNorm + ELU (fp16 X) ----------------
__global__ void k_zero_bn() {
    int c = threadIdx.x;
    g_bns[c] = 0.f;
    g_bnq[c] = 0.f;
}
__global__ void k_bn_stats(const __half* __restrict__ X) {
    int c = threadIdx.x;
    int r0 = blockIdx.x * 256;
    int r1 = min(r0 + 256, NN);
    float s = 0.f, q = 0.f;
    for (int r = r0; r < r1; r++) {
        float v = __half2float(X[(size_t)r * DD + c]);
        s += v; q += v * v;
    }
    atomicAdd(&g_bns[c], s);
    atomicAdd(&g_bnq[c], q);
}
__global__ void k_bn_apply(__half* __restrict__ X,
                           const float* __restrict__ gamma,
                           const float* __restrict__ beta) {
    int idx = blockIdx.x * 256 + threadIdx.x;       // over NN*128 half2s
    if (idx >= NN * (DD / 2)) return;
    int c2 = idx & 127;
    int c = c2 * 2;
    const float invN = 1.f / (float)NN;
    float2 sm = *(const float2*)&g_bns[c];
    float2 sq = *(const float2*)&g_bnq[c];
    float2 gm = *(const float2*)&gamma[c];
    float2 bt = *(const float2*)&beta[c];
    __half2 hx = ((__half2*)X)[idx];
    float2 x = __half22float2(hx);
    float mu, var, sc;
    float2 y;
    mu = sm.x * invN; var = sq.x * invN - mu * mu; sc = gm.x * rsqrtf(var + 1e-5f);
    y.x = sc * (x.x - mu) + bt.x;
    mu = sm.y * invN; var = sq.y * invN - mu * mu; sc = gm.y * rsqrtf(var + 1e-5f);
    y.y = sc * (x.y - mu) + bt.y;
    y.x = (y.x > 0.f) ? y.x : (__expf(y.x) - 1.f);
    y.y = (y.y > 0.f) ? y.y : (fexp_neg(y.y) - 1.f);
    ((__half2*)X)[idx] = __floats2half2_rn(y.x, y.y);
}

// ---------------- logits GEMM (reads fp32 out) ----------------
__global__ __launch_bounds__(320) void k_logits(
    const float* __restrict__ X, const float* __restrict__ W,
    const float* __restrict__ bias, float* __restrict__ O, int M)
{
    __shared__ float Xs[32][68];
    __shared__ float Ws[32][40];
    int tid = threadIdx.x;
    int bm0 = blockIdx.x * 64;
    int rg = tid / 40;
    int col = tid % 40;
    float acc[8];
    #pragma unroll
    for (int i = 0; i < 8; i++) acc[i] = 0.f;

    for (int k0 = 0; k0 < DD; k0 += 32) {
        for (int idx = tid; idx < 512; idx += 320) {
            int row = idx >> 3;
            int kq = idx & 7;
            float4 v = make_float4(0.f, 0.f, 0.f, 0.f);
            int gr = bm0 + row;
            if (gr < M) v = *(const float4*)(X + (size_t)gr * DD + k0 + kq * 4);
            Xs[kq * 4 + 0][row] = v.x;
            Xs[kq * 4 + 1][row] = v.y;
            Xs[kq * 4 + 2][row] = v.z;
            Xs[kq * 4 + 3][row] = v.w;
        }
        for (int idx = tid; idx < 1280; idx += 320) {
            int k = idx / 40, c = idx % 40;
            Ws[k][c] = W[(size_t)(k0 + k) * CC + c];
        }
        __syncthreads();
        #pragma unroll
        for (int kk = 0; kk < 32; kk++) {
            float w = Ws[kk][col];
            float a0[4], a1[4];
            *(float4*)&a0[0] = *(float4*)&Xs[kk][rg * 8];
            *(float4*)&a1[0] = *(float4*)&Xs[kk][rg * 8 + 4];
            acc[0] += a0[0] * w; acc[1] += a0[1] * w;
            acc[2] += a0[2] * w; acc[3] += a0[3] * w;
            acc[4] += a1[0] * w; acc[5] += a1[1] * w;
            acc[6] += a1[2] * w; acc[7] += a1[3] * w;
        }
        __syncthreads();
    }
    float b = bias[col];
    #pragma unroll
    for (int i = 0; i < 8; i++) {
        int r = bm0 + rg * 8 + i;
        if (r < M) O[(size_t)r * CC + col] = acc[i] + b;
    }
}

// ---------------- static stream/event init ----------------
struct SideRes {
    cudaStream_t sB;
    cudaEvent_t evFork, evJoin;
    SideRes() {
        cudaStreamCreateWithFlags(&sB, cudaStreamNonBlocking);
        cudaEventCreateWithFlags(&evFork, cudaEventDisableTiming);
        cudaEventCreateWithFlags(&evJoin, cudaEventDisableTiming);
        cudaFuncSetAttribute(hmma_gemm_fc, cudaFuncAttributeMaxDynamicSharedMemorySize, SMEM_GEMM);
        cudaFuncSetAttribute(hmma_gemm_pk<true>,  cudaFuncAttributeMaxDynamicSharedMemorySize, SMEM_GEMM);
        cudaFuncSetAttribute(hmma_gemm_pk<false>, cudaFuncAttributeMaxDynamicSharedMemorySize, SMEM_GEMM);
    }
};
static SideRes g_sr;

// ---------------- driver ----------------
extern "C" void kernel_launch(void* const* d_in, const int* in_sizes, int n_in,
                              void* d_out, int out_size)
{
    const float* feat  = (const float*)d_in[0];
    const int*   src   = (const int*)d_in[1];
    const int*   dst   = (const int*)d_in[2];
    const float* W_fc  = (const float*)d_in[3];
    const float* b_fc  = (const float*)d_in[4];
    const float* W1    = (const float*)d_in[5];
    const float* b1    = (const float*)d_in[6];
    const float* W2    = (const float*)d_in[7];
    const float* b2    = (const float*)d_in[8];
    const float* W3    = (const float*)d_in[9];
    const float* b3    = (const float*)d_in[10];
    const float* gamma = (const float*)d_in[11];
    const float* beta  = (const float*)d_in[12];
    const float* W_lin = (const float*)d_in[13];
    const float* b_lin = (const float*)d_in[14];
    float* out = (float*)d_out;

    __half* gX16; cudaGetSymbolAddress((void**)&gX16, g_X16);
    unsigned char *gAh, *gAl;
    cudaGetSymbolAddress((void**)&gAh, g_Ah);
    cudaGetSymbolAddress((void**)&gAl, g_Al);
    unsigned char *pFh, *pFl, *p1h, *p1l, *p2h, *p2l, *p3h, *p3l;
    cudaGetSymbolAddress((void**)&pFh, g_Wfc_h);
    cudaGetSymbolAddress((void**)&pFl, g_Wfc_l);
    cudaGetSymbolAddress((void**)&p1h, g_W1_h);
    cudaGetSymbolAddress((void**)&p1l, g_W1_l);
    cudaGetSymbolAddress((void**)&p2h, g_W2_h);
    cudaGetSymbolAddress((void**)&p2l, g_W2_l);
    cudaGetSymbolAddress((void**)&p3h, g_W3_h);
    cudaGetSymbolAddress((void**)&p3l, g_W3_l);

    const int NB_N = (NN + 255) / 256;
    const int NB_E = (EE + 255) / 256;
    const int GEMM_GRID = (NN + 63) / 64;   // 782
    dim3 spmm_block(32, 8);
    int spmm_grid = (NN + 7) / 8;
    int bn_grid = (NN * (DD / 2) + 255) / 256;

    // fork
    cudaEventRecord(g_sr.evFork, 0);
    cudaStreamWaitEvent(g_sr.sB, g_sr.evFork, 0);

    k_zero_prep<<<NB_N, 256, 0, g_sr.sB>>>();
    k_count<<<NB_E, 256, 0, g_sr.sB>>>(src, dst);
    k_prepack<<<(DD * (FF / 8) + 255) / 256, 256>>>(W_fc, pFh, pFl, FF);              // main
    hmma_gemm_fc<<<GEMM_GRID, 256, SMEM_GEMM>>>(feat, pFh, pFl, b_fc, gX16, NN, FF);  // main
    k_norms<<<NB_N, 256, 0, g_sr.sB>>>();
    k_scan1<<<49, 1024, 0, g_sr.sB>>>();
    k_scan2<<<1, 64, 0, g_sr.sB>>>();
    k_scan3<<<NB_N, 256, 0, g_sr.sB>>>();
    k_fill<<<NB_E, 256, 0, g_sr.sB>>>(src, dst);
    k_prepack<<<(DD * (DD / 8) + 255) / 256, 256, 0, g_sr.sB>>>(W1, p1h, p1l, DD);
    k_prepack<<<(DD * (DD / 8) + 255) / 256, 256, 0, g_sr.sB>>>(W2, p2h, p2l, DD);
    k_prepack<<<(DD * (DD / 8) + 255) / 256, 256, 0, g_sr.sB>>>(W3, p3h, p3l, DD);
    k_zero_bn<<<1, 256, 0, g_sr.sB>>>();
    cudaEventRecord(g_sr.evJoin, g_sr.sB);

    // join
    cudaStreamWaitEvent(0, g_sr.evJoin, 0);

    // layer 1
    k_spmm<<<spmm_grid, spmm_block>>>(gX16);
    hmma_gemm_pk<true><<<GEMM_GRID, 256, SMEM_GEMM>>>(gAh, gAl, p1h, p1l, b1, gX16, NN);
    k_bn_stats<<<NB_N, 256>>>(gX16);
    k_bn_apply<<<bn_grid, 256>>>(gX16, gamma, beta);
    k_zero_bn<<<1, 256>>>();

    // layer 2
    k_spmm<<<spmm_grid, spmm_block>>>(gX16);
    hmma_gemm_pk<true><<<GEMM_GRID, 256, SMEM_GEMM>>>(gAh, gAl, p2h, p2l, b2, gX16, NN);
    k_bn_stats<<<NB_N, 256>>>(gX16);
    k_bn_apply<<<bn_grid, 256>>>(gX16, gamma, beta);

    // layer 3 -> fp32 features into d_out[0 : N*D)
    k_spmm<<<spmm_grid, spmm_block>>>(gX16);
    hmma_gemm_pk<false><<<GEMM_GRID, 256, SMEM_GEMM>>>(gAh, gAl, p3h, p3l, b3, out, NN);

    // logits -> d_out[N*D : )
    k_logits<<<(NN + 63) / 64, 320>>>(out, W_lin, b_lin, out + (size_t)NN * DD, NN);
}